// round 7
// baseline (speedup 1.0000x reference)
#include <cuda_runtime.h>
#include <math.h>

#define BATCH 8
#define SS 1048576              // 128*128*64
#define NTOT (BATCH * SS)       // 8388608 per component

// ---------------- scratch (device globals; no allocation) ----------------
__device__ float g_s_re[NTOT];
__device__ float g_s_im[NTOT];
__device__ float g_u_re[NTOT];
__device__ float g_u_im[NTOT];
__device__ float g_l_re[NTOT];
__device__ float g_l_im[NTOT];
__device__ float g_p_re[4194304];   // split-K partials (NC*B*d*d max)
__device__ float g_p_im[4194304];
__device__ float g_m_re[131072];    // routing matrix (B*d*d max)
__device__ float g_m_im[131072];

typedef unsigned long long u64;

// ---------------- f32x2 packed helpers ------------------------------------
__device__ __forceinline__ void fma2(u64& d, u64 a, u64 b) {
    asm("fma.rn.f32x2 %0, %1, %2, %3;" : "=l"(d) : "l"(a), "l"(b), "l"(d));
}
__device__ __forceinline__ void add2(u64& d, u64 a, u64 b) {
    asm("add.rn.f32x2 %0, %1, %2;" : "=l"(d) : "l"(a), "l"(b));
}
__device__ __forceinline__ void lds2(u64& lo, u64& hi, const float* p) {
    unsigned a = (unsigned)__cvta_generic_to_shared(p);
    asm volatile("ld.shared.v2.b64 {%0,%1}, [%2];" : "=l"(lo), "=l"(hi) : "r"(a));
}
__device__ __forceinline__ void unpack2(float& lo, float& hi, u64 v) {
    unsigned a, b;
    asm("mov.b64 {%0,%1}, %2;" : "=r"(a), "=r"(b) : "l"(v));
    lo = __uint_as_float(a); hi = __uint_as_float(b);
}

// ======================= NN kernel: C[b] = A(b?) * U[b] ====================
// tile: BM=64, BN=128, BK=16; 256 threads; per-thread 4(M) x 8(N)
// Karatsuba: T1=ar*br, T2=ai*bi, T3=(ar+ai)(br+bi); cr=T1-T2, ci=T3-T1-T2
#define NN_APAD 132     // 64 m-values duplicated -> 128 floats + 4 pad
#define NN_BPAD 136     // 128 cols + 8 pad

__global__ __launch_bounds__(256, 1)
void cgemm_nn(const float* __restrict__ Are, const float* __restrict__ Aim, int strideA,
              const float* __restrict__ Ure, const float* __restrict__ Uim,
              float* __restrict__ Cre, float* __restrict__ Cim,
              int d, int rest)
{
    __shared__ __align__(16) float Adr[16][NN_APAD], Adi[16][NN_APAD], Ads[16][NN_APAD];
    __shared__ __align__(16) float Bre[16][NN_BPAD], Bim[16][NN_BPAD];

    const int b  = blockIdx.z;
    const int m0 = blockIdx.y * 64;
    const int n0 = blockIdx.x * 128;

    const float* are = Are + (size_t)b * strideA;
    const float* aim = Aim + (size_t)b * strideA;
    const float* ure = Ure + (size_t)b * d * rest + n0;
    const float* uim = Uim + (size_t)b * d * rest + n0;
    float*       cre = Cre + (size_t)b * d * rest + n0;
    float*       cim = Cim + (size_t)b * d * rest + n0;

    const int tid = threadIdx.x;
    const int tn4 = (tid & 15) * 4;     // frag cols: [tn4..tn4+3] and [64+tn4..]
    const int tm  = tid >> 4;           // rows tm*4..tm*4+3
    const int tm8 = tm * 8;             // dup-offset into A rows
    const int brr = tid >> 4;           // B loader row 0..15
    const int bc4 = (tid & 15) * 4;     // B loader col
    const int arr = tid >> 2;           // A loader row 0..63
    const int ac4 = (tid & 3) * 4;      // A loader k-col

    u64 T1[4][4], T2[4][4], T3[4][4];
#pragma unroll
    for (int i = 0; i < 4; i++)
#pragma unroll
        for (int c = 0; c < 4; c++) { T1[i][c] = 0ULL; T2[i][c] = 0ULL; T3[i][c] = 0ULL; }

    // prefetch first tile
    float4 pb0r = *(const float4*)(ure + (size_t)brr * rest + bc4);
    float4 pb1r = *(const float4*)(ure + (size_t)brr * rest + 64 + bc4);
    float4 pb0i = *(const float4*)(uim + (size_t)brr * rest + bc4);
    float4 pb1i = *(const float4*)(uim + (size_t)brr * rest + 64 + bc4);
    float4 par  = *(const float4*)(are + (size_t)(m0 + arr) * d + ac4);
    float4 pai  = *(const float4*)(aim + (size_t)(m0 + arr) * d + ac4);

    for (int kk = 0; kk < d; kk += 16) {
        *(float4*)&Bre[brr][bc4]      = pb0r;
        *(float4*)&Bre[brr][64 + bc4] = pb1r;
        *(float4*)&Bim[brr][bc4]      = pb0i;
        *(float4*)&Bim[brr][64 + bc4] = pb1i;
        {
            const float* pr = (const float*)&par;
            const float* pi = (const float*)&pai;
#pragma unroll
            for (int j = 0; j < 4; j++) {
                float vr = pr[j], vi = pi[j];
                *(float2*)&Adr[ac4 + j][2 * arr] = make_float2(vr, vr);
                *(float2*)&Adi[ac4 + j][2 * arr] = make_float2(vi, vi);
                float vs = vr + vi;
                *(float2*)&Ads[ac4 + j][2 * arr] = make_float2(vs, vs);
            }
        }
        __syncthreads();

        if (kk + 16 < d) {
            pb0r = *(const float4*)(ure + (size_t)(kk + 16 + brr) * rest + bc4);
            pb1r = *(const float4*)(ure + (size_t)(kk + 16 + brr) * rest + 64 + bc4);
            pb0i = *(const float4*)(uim + (size_t)(kk + 16 + brr) * rest + bc4);
            pb1i = *(const float4*)(uim + (size_t)(kk + 16 + brr) * rest + 64 + bc4);
            par  = *(const float4*)(are + (size_t)(m0 + arr) * d + kk + 16 + ac4);
            pai  = *(const float4*)(aim + (size_t)(m0 + arr) * d + kk + 16 + ac4);
        }

#pragma unroll
        for (int k = 0; k < 16; k++) {
            u64 br0, br1, br2, br3, bi0, bi1, bi2, bi3, bs0, bs1, bs2, bs3;
            u64 a0, a1, a2, a3;
            lds2(br0, br1, &Bre[k][tn4]);
            lds2(br2, br3, &Bre[k][64 + tn4]);
            lds2(bi0, bi1, &Bim[k][tn4]);
            lds2(bi2, bi3, &Bim[k][64 + tn4]);
            add2(bs0, br0, bi0); add2(bs1, br1, bi1);
            add2(bs2, br2, bi2); add2(bs3, br3, bi3);

            lds2(a0, a1, &Adr[k][tm8]);
            lds2(a2, a3, &Adr[k][tm8 + 4]);
            fma2(T1[0][0], a0, br0); fma2(T1[0][1], a0, br1); fma2(T1[0][2], a0, br2); fma2(T1[0][3], a0, br3);
            fma2(T1[1][0], a1, br0); fma2(T1[1][1], a1, br1); fma2(T1[1][2], a1, br2); fma2(T1[1][3], a1, br3);
            fma2(T1[2][0], a2, br0); fma2(T1[2][1], a2, br1); fma2(T1[2][2], a2, br2); fma2(T1[2][3], a2, br3);
            fma2(T1[3][0], a3, br0); fma2(T1[3][1], a3, br1); fma2(T1[3][2], a3, br2); fma2(T1[3][3], a3, br3);

            lds2(a0, a1, &Adi[k][tm8]);
            lds2(a2, a3, &Adi[k][tm8 + 4]);
            fma2(T2[0][0], a0, bi0); fma2(T2[0][1], a0, bi1); fma2(T2[0][2], a0, bi2); fma2(T2[0][3], a0, bi3);
            fma2(T2[1][0], a1, bi0); fma2(T2[1][1], a1, bi1); fma2(T2[1][2], a1, bi2); fma2(T2[1][3], a1, bi3);
            fma2(T2[2][0], a2, bi0); fma2(T2[2][1], a2, bi1); fma2(T2[2][2], a2, bi2); fma2(T2[2][3], a2, bi3);
            fma2(T2[3][0], a3, bi0); fma2(T2[3][1], a3, bi1); fma2(T2[3][2], a3, bi2); fma2(T2[3][3], a3, bi3);

            lds2(a0, a1, &Ads[k][tm8]);
            lds2(a2, a3, &Ads[k][tm8 + 4]);
            fma2(T3[0][0], a0, bs0); fma2(T3[0][1], a0, bs1); fma2(T3[0][2], a0, bs2); fma2(T3[0][3], a0, bs3);
            fma2(T3[1][0], a1, bs0); fma2(T3[1][1], a1, bs1); fma2(T3[1][2], a1, bs2); fma2(T3[1][3], a1, bs3);
            fma2(T3[2][0], a2, bs0); fma2(T3[2][1], a2, bs1); fma2(T3[2][2], a2, bs2); fma2(T3[2][3], a2, bs3);
            fma2(T3[3][0], a3, bs0); fma2(T3[3][1], a3, bs1); fma2(T3[3][2], a3, bs2); fma2(T3[3][3], a3, bs3);
        }
        __syncthreads();
    }

#pragma unroll
    for (int i = 0; i < 4; i++) {
        int m = m0 + tm * 4 + i;
        float re[8], im_[8];
#pragma unroll
        for (int c = 0; c < 4; c++) {
            float t1l, t1h, t2l, t2h, t3l, t3h;
            unpack2(t1l, t1h, T1[i][c]);
            unpack2(t2l, t2h, T2[i][c]);
            unpack2(t3l, t3h, T3[i][c]);
            re[2 * c]     = t1l - t2l;
            re[2 * c + 1] = t1h - t2h;
            im_[2 * c]     = t3l - t1l - t2l;
            im_[2 * c + 1] = t3h - t1h - t2h;
        }
        *(float4*)(cre + (size_t)m * rest + tn4)      = make_float4(re[0], re[1], re[2], re[3]);
        *(float4*)(cre + (size_t)m * rest + 64 + tn4) = make_float4(re[4], re[5], re[6], re[7]);
        *(float4*)(cim + (size_t)m * rest + tn4)      = make_float4(im_[0], im_[1], im_[2], im_[3]);
        *(float4*)(cim + (size_t)m * rest + 64 + tn4) = make_float4(im_[4], im_[5], im_[6], im_[7]);
    }
}

// ============ NT split-K: P[chunk][b] = L[b] * U[b]^T (K chunk) ============
// tile: BM=64, BN=64, BK=16; 256 threads; per-thread 4(M) x 4(N)
__global__ __launch_bounds__(256, 2)
void cgemm_nt(const float* __restrict__ Lre, const float* __restrict__ Lim,
              const float* __restrict__ Ure, const float* __restrict__ Uim,
              float* __restrict__ Pre, float* __restrict__ Pim,
              int d, int K, int KC)
{
    __shared__ __align__(16) float Adr[16][NN_APAD], Adi[16][NN_APAD], Ads[16][NN_APAD];
    __shared__ __align__(16) float Bre[16][68], Bim[16][68];

    const int bz    = blockIdx.z;
    const int b     = bz & 7;
    const int chunk = bz >> 3;
    const int m0    = blockIdx.y * 64;
    const int n0    = blockIdx.x * 64;

    const float* lre = Lre + (size_t)b * d * K;
    const float* lim = Lim + (size_t)b * d * K;
    const float* ure = Ure + (size_t)b * d * K;
    const float* uim = Uim + (size_t)b * d * K;

    const int tid = threadIdx.x;
    const int tn4 = (tid & 15) * 4;
    const int tm  = tid >> 4;
    const int tm8 = tm * 8;
    const int lrr = tid >> 2;           // loader row 0..63 (both A and B)
    const int lc4 = (tid & 3) * 4;      // loader k-col

    u64 T1[4][2], T2[4][2], T3[4][2];
#pragma unroll
    for (int i = 0; i < 4; i++)
#pragma unroll
        for (int c = 0; c < 2; c++) { T1[i][c] = 0ULL; T2[i][c] = 0ULL; T3[i][c] = 0ULL; }

    const int kbeg = chunk * KC;
    const int kend = kbeg + KC;

    float4 par = *(const float4*)(lre + (size_t)(m0 + lrr) * K + kbeg + lc4);
    float4 pai = *(const float4*)(lim + (size_t)(m0 + lrr) * K + kbeg + lc4);
    float4 pbr = *(const float4*)(ure + (size_t)(n0 + lrr) * K + kbeg + lc4);
    float4 pbi = *(const float4*)(uim + (size_t)(n0 + lrr) * K + kbeg + lc4);

    for (int kk = kbeg; kk < kend; kk += 16) {
        {
            const float* pr = (const float*)&par;
            const float* pi = (const float*)&pai;
            const float* qr = (const float*)&pbr;
            const float* qi = (const float*)&pbi;
#pragma unroll
            for (int j = 0; j < 4; j++) {
                float vr = pr[j], vi = pi[j];
                *(float2*)&Adr[lc4 + j][2 * lrr] = make_float2(vr, vr);
                *(float2*)&Adi[lc4 + j][2 * lrr] = make_float2(vi, vi);
                float vs = vr + vi;
                *(float2*)&Ads[lc4 + j][2 * lrr] = make_float2(vs, vs);
                Bre[lc4 + j][lrr] = qr[j];
                Bim[lc4 + j][lrr] = qi[j];
            }
        }
        __syncthreads();

        if (kk + 16 < kend) {
            par = *(const float4*)(lre + (size_t)(m0 + lrr) * K + kk + 16 + lc4);
            pai = *(const float4*)(lim + (size_t)(m0 + lrr) * K + kk + 16 + lc4);
            pbr = *(const float4*)(ure + (size_t)(n0 + lrr) * K + kk + 16 + lc4);
            pbi = *(const float4*)(uim + (size_t)(n0 + lrr) * K + kk + 16 + lc4);
        }

#pragma unroll
        for (int k = 0; k < 16; k++) {
            u64 br0, br1, bi0, bi1, bs0, bs1, a0, a1, a2, a3;
            lds2(br0, br1, &Bre[k][tn4]);
            lds2(bi0, bi1, &Bim[k][tn4]);
            add2(bs0, br0, bi0); add2(bs1, br1, bi1);

            lds2(a0, a1, &Adr[k][tm8]);
            lds2(a2, a3, &Adr[k][tm8 + 4]);
            fma2(T1[0][0], a0, br0); fma2(T1[0][1], a0, br1);
            fma2(T1[1][0], a1, br0); fma2(T1[1][1], a1, br1);
            fma2(T1[2][0], a2, br0); fma2(T1[2][1], a2, br1);
            fma2(T1[3][0], a3, br0); fma2(T1[3][1], a3, br1);

            lds2(a0, a1, &Adi[k][tm8]);
            lds2(a2, a3, &Adi[k][tm8 + 4]);
            fma2(T2[0][0], a0, bi0); fma2(T2[0][1], a0, bi1);
            fma2(T2[1][0], a1, bi0); fma2(T2[1][1], a1, bi1);
            fma2(T2[2][0], a2, bi0); fma2(T2[2][1], a2, bi1);
            fma2(T2[3][0], a3, bi0); fma2(T2[3][1], a3, bi1);

            lds2(a0, a1, &Ads[k][tm8]);
            lds2(a2, a3, &Ads[k][tm8 + 4]);
            fma2(T3[0][0], a0, bs0); fma2(T3[0][1], a0, bs1);
            fma2(T3[1][0], a1, bs0); fma2(T3[1][1], a1, bs1);
            fma2(T3[2][0], a2, bs0); fma2(T3[2][1], a2, bs1);
            fma2(T3[3][0], a3, bs0); fma2(T3[3][1], a3, bs1);
        }
        __syncthreads();
    }

    size_t off = (size_t)(chunk * BATCH + b) * d * d;
#pragma unroll
    for (int i = 0; i < 4; i++) {
        int m = m0 + tm * 4 + i;
        float re[4], im_[4];
#pragma unroll
        for (int c = 0; c < 2; c++) {
            float t1l, t1h, t2l, t2h, t3l, t3h;
            unpack2(t1l, t1h, T1[i][c]);
            unpack2(t2l, t2h, T2[i][c]);
            unpack2(t3l, t3h, T3[i][c]);
            re[2 * c]     = t1l - t2l;
            re[2 * c + 1] = t1h - t2h;
            im_[2 * c]     = t3l - t1l - t2l;
            im_[2 * c + 1] = t3h - t1h - t2h;
        }
        *(float4*)(Pre + off + (size_t)m * d + n0 + tn4) = make_float4(re[0], re[1], re[2], re[3]);
        *(float4*)(Pim + off + (size_t)m * d + n0 + tn4) = make_float4(im_[0], im_[1], im_[2], im_[3]);
    }
}

// ---------------- fused split-K reduce + softmax(|s|/scale)*phase ---------
__global__ void softmax_fused(const float* __restrict__ Pre, const float* __restrict__ Pim,
                              float* __restrict__ Mre, float* __restrict__ Mim,
                              int d, int n, int nchunks,
                              const float* __restrict__ logtau, float sfac)
{
    const int row = blockIdx.x;
    const int j   = threadIdx.x;
    const int idx = row * d + j;

    float sr = 0.f, si = 0.f;
    for (int c = 0; c < nchunks; c++) {
        sr += Pre[(size_t)c * n + idx];
        si += Pim[(size_t)c * n + idx];
    }
    const float mag = sqrtf(sr * sr + si * si);

    const float tau   = fmaxf(expf(logtau[0]), 1e-8f);
    const float scale = tau * sfac;
    const float logit = mag / scale;

    __shared__ float wred[4];
    __shared__ float wsum[4];
    const int warp = j >> 5, lane = j & 31, nw = d >> 5;

    float v = logit;
#pragma unroll
    for (int o = 16; o > 0; o >>= 1) v = fmaxf(v, __shfl_xor_sync(0xffffffffu, v, o));
    if (lane == 0) wred[warp] = v;
    __syncthreads();
    float mx = wred[0];
    for (int w = 1; w < nw; w++) mx = fmaxf(mx, wred[w]);

    const float e = expf(logit - mx);
    float s_ = e;
#pragma unroll
    for (int o = 16; o > 0; o >>= 1) s_ += __shfl_xor_sync(0xffffffffu, s_, o);
    if (lane == 0) wsum[warp] = s_;
    __syncthreads();
    float tot = 0.f;
    for (int w = 0; w < nw; w++) tot += wsum[w];

    const float routing = e / tot;
    float pr, pi;
    if (mag > 1e-8f) { pr = sr / mag; pi = si / mag; }
    else             { pr = 1.f;      pi = 0.f; }
    Mre[(size_t)row * d + j] = routing * pr;
    Mim[(size_t)row * d + j] = routing * pi;
}

// ---------------- mode-1 permute (float4): swap the two 128-axes ----------
__global__ void perm_swap01(const float4* __restrict__ s4re, const float4* __restrict__ s4im,
                            float4* __restrict__ d4re, float4* __restrict__ d4im)
{
    int t = blockIdx.x * 256 + threadIdx.x;     // < NTOT/4 = 2097152
    int k4 = t & 15;
    int q  = (t >> 4) & 127;
    int p  = (t >> 11) & 127;
    int b  = t >> 18;
    int src = ((((b << 7) | q) << 7) | p) << 4 | k4;
    d4re[t] = s4re[src];
    d4im[t] = s4im[src];
}

// ---------------- batched 2D transpose: dst[b][c][r] = src[b][r][c] -------
__global__ void perm_transpose(const float* __restrict__ sre, const float* __restrict__ sim,
                               float* __restrict__ dre, float* __restrict__ dim_,
                               int R, int C)
{
    __shared__ float tre[32][33], tim[32][33];
    const int b  = blockIdx.z;
    const int r0 = blockIdx.y * 32;
    const int c0 = blockIdx.x * 32;
    const float* sr_ = sre + (size_t)b * R * C;
    const float* si_ = sim + (size_t)b * R * C;
    float*       dr_ = dre + (size_t)b * R * C;
    float*       di_ = dim_ + (size_t)b * R * C;
    const int x = threadIdx.x, y = threadIdx.y;    // 32 x 8
#pragma unroll
    for (int i = y; i < 32; i += 8) {
        tre[i][x] = sr_[(size_t)(r0 + i) * C + c0 + x];
        tim[i][x] = si_[(size_t)(r0 + i) * C + c0 + x];
    }
    __syncthreads();
#pragma unroll
    for (int i = y; i < 32; i += 8) {
        dr_[(size_t)(c0 + i) * R + r0 + x] = tre[x][i];
        di_[(size_t)(c0 + i) * R + r0 + x] = tim[x][i];
    }
}

// --------------------------------------------------------------------------
extern "C" void kernel_launch(void* const* d_in, const int* in_sizes, int n_in,
                              void* d_out, int out_size)
{
    (void)in_sizes; (void)n_in; (void)out_size;
    const float* xre  = (const float*)d_in[0];
    const float* xim  = (const float*)d_in[1];
    const float* w0re = (const float*)d_in[2];
    const float* w0im = (const float*)d_in[3];
    const float* w1re = (const float*)d_in[4];
    const float* w1im = (const float*)d_in[5];
    const float* w2re = (const float*)d_in[6];
    const float* w2im = (const float*)d_in[7];
    const float* ltau = (const float*)d_in[8];
    float* out_re = (float*)d_out;
    float* out_im = out_re + (size_t)NTOT;

    float *s_re, *s_im, *u_re, *u_im, *l_re, *l_im, *p_re, *p_im, *m_re, *m_im;
    cudaGetSymbolAddress((void**)&s_re,  g_s_re);
    cudaGetSymbolAddress((void**)&s_im,  g_s_im);
    cudaGetSymbolAddress((void**)&u_re,  g_u_re);
    cudaGetSymbolAddress((void**)&u_im,  g_u_im);
    cudaGetSymbolAddress((void**)&l_re,  g_l_re);
    cudaGetSymbolAddress((void**)&l_im,  g_l_im);
    cudaGetSymbolAddress((void**)&p_re,  g_p_re);
    cudaGetSymbolAddress((void**)&p_im,  g_p_im);
    cudaGetSymbolAddress((void**)&m_re,  g_m_re);
    cudaGetSymbolAddress((void**)&m_im,  g_m_im);

    // ---------------- Mode 0: d=128, rest=8192 (unfold = identity) --------
    {
        const int d = 128, rest = 8192;
        dim3 g1(rest / 128, d / 64, BATCH);
        cgemm_nn<<<g1, 256>>>(w0re, w0im, 0, xre, xim, l_re, l_im, d, rest);

        const int NC = 32, KC = rest / NC;        // 256
        dim3 g2(d / 64, d / 64, BATCH * NC);
        cgemm_nt<<<g2, 256>>>(l_re, l_im, xre, xim, p_re, p_im, d, rest, KC);

        const int n = BATCH * d * d;
        softmax_fused<<<BATCH * d, d>>>(p_re, p_im, m_re, m_im, d, n, NC, ltau,
                                        sqrtf((float)SS / (float)d));
        cgemm_nn<<<g1, 256>>>(m_re, m_im, d * d, xre, xim, s_re, s_im, d, rest);
    }

    // ---------------- Mode 1: d=128, rest=8192 ----------------------------
    {
        const int d = 128, rest = 8192;
        perm_swap01<<<(NTOT / 4) / 256, 256>>>((const float4*)s_re, (const float4*)s_im,
                                               (float4*)u_re, (float4*)u_im);

        dim3 g1(rest / 128, d / 64, BATCH);
        cgemm_nn<<<g1, 256>>>(w1re, w1im, 0, u_re, u_im, l_re, l_im, d, rest);

        const int NC = 32, KC = rest / NC;
        dim3 g2(d / 64, d / 64, BATCH * NC);
        cgemm_nt<<<g2, 256>>>(l_re, l_im, u_re, u_im, p_re, p_im, d, rest, KC);

        const int n = BATCH * d * d;
        softmax_fused<<<BATCH * d, d>>>(p_re, p_im, m_re, m_im, d, n, NC, ltau,
                                        sqrtf((float)SS / (float)d));
        cgemm_nn<<<g1, 256>>>(m_re, m_im, d * d, u_re, u_im, l_re, l_im, d, rest);
        perm_swap01<<<(NTOT / 4) / 256, 256>>>((const float4*)l_re, (const float4*)l_im,
                                               (float4*)s_re, (float4*)s_im);
    }

    // ---------------- Mode 2: d=64, rest=16384 ----------------------------
    {
        const int d = 64, rest = 16384;
        // unfold: u[b, k, p] = s[b, p, k]   (src R=16384, C=64)
        dim3 gt(64 / 32, 16384 / 32, BATCH);
        perm_transpose<<<gt, dim3(32, 8)>>>(s_re, s_im, u_re, u_im, 16384, 64);

        dim3 g1(rest / 128, d / 64, BATCH);
        cgemm_nn<<<g1, 256>>>(w2re, w2im, 0, u_re, u_im, l_re, l_im, d, rest);

        const int NC = 64, KC = rest / NC;        // 256
        dim3 g2(d / 64, d / 64, BATCH * NC);
        cgemm_nt<<<g2, 256>>>(l_re, l_im, u_re, u_im, p_re, p_im, d, rest, KC);

        const int n = BATCH * d * d;
        softmax_fused<<<BATCH * d, d>>>(p_re, p_im, m_re, m_im, d, n, NC, ltau,
                                        sqrtf((float)SS / (float)d));
        cgemm_nn<<<g1, 256>>>(m_re, m_im, d * d, u_re, u_im, l_re, l_im, d, rest);

        // fold: out[b, p, k] = mixed[b, k, p]   (src R=64, C=16384) -> d_out
        dim3 gt2(16384 / 32, 64 / 32, BATCH);
        perm_transpose<<<gt2, dim3(32, 8)>>>(l_re, l_im, out_re, out_im, 64, 16384);
    }
}

// round 8
// speedup vs baseline: 1.0058x; 1.0058x over previous
#include <cuda_runtime.h>
#include <math.h>

#define BATCH 8
#define SS 1048576              // 128*128*64
#define NTOT (BATCH * SS)       // 8388608 per component

// ---------------- scratch (device globals; no allocation) ----------------
__device__ float g_s_re[NTOT];
__device__ float g_s_im[NTOT];
__device__ float g_u_re[NTOT];
__device__ float g_u_im[NTOT];
__device__ float g_l_re[NTOT];
__device__ float g_l_im[NTOT];
__device__ float g_p_re[4194304];   // split-K partials (NC*B*d*d max)
__device__ float g_p_im[4194304];
__device__ float g_m_re[131072];    // routing matrix (B*d*d max)
__device__ float g_m_im[131072];

typedef unsigned long long u64;

// ---------------- f32x2 packed helpers ------------------------------------
__device__ __forceinline__ void fma2(u64& d, u64 a, u64 b) {
    asm("fma.rn.f32x2 %0, %1, %2, %3;" : "=l"(d) : "l"(a), "l"(b), "l"(d));
}
__device__ __forceinline__ void add2(u64& d, u64 a, u64 b) {
    asm("add.rn.f32x2 %0, %1, %2;" : "=l"(d) : "l"(a), "l"(b));
}
__device__ __forceinline__ void lds2(u64& lo, u64& hi, const float* p) {
    unsigned a = (unsigned)__cvta_generic_to_shared(p);
    asm volatile("ld.shared.v2.b64 {%0,%1}, [%2];" : "=l"(lo), "=l"(hi) : "r"(a));
}
__device__ __forceinline__ void unpack2(float& lo, float& hi, u64 v) {
    unsigned a, b;
    asm("mov.b64 {%0,%1}, %2;" : "=r"(a), "=r"(b) : "l"(v));
    lo = __uint_as_float(a); hi = __uint_as_float(b);
}

#define APAD 132     // 64 m-values duplicated -> 128 floats + 4 pad (row = 528B, 16B-mult)
#define BPAD 68      // 64 cols + 4 pad (row = 272B, 16B-mult)

// ======================= NN kernel: C[b] = A(b?) * U[b] ====================
// tile: BM=64, BN=64, BK=16; 256 threads; per-thread 4(M) x 4(N); 2 CTAs/SM
// Karatsuba: T1=ar*br, T2=ai*bi, T3=(ar+ai)(br+bi); cr=T1-T2, ci=T3-T1-T2
// A stored duplicated-pair (f32x2-ready broadcast); B-sum computed in regs.
__global__ __launch_bounds__(256, 2)
void cgemm_nn(const float* __restrict__ Are, const float* __restrict__ Aim, int strideA,
              const float* __restrict__ Ure, const float* __restrict__ Uim,
              float* __restrict__ Cre, float* __restrict__ Cim,
              int d, int rest)
{
    __shared__ __align__(16) float Adr[16][APAD], Adi[16][APAD], Ads[16][APAD];
    __shared__ __align__(16) float Bre[16][BPAD], Bim[16][BPAD];

    const int b  = blockIdx.z;
    const int m0 = blockIdx.y * 64;
    const int n0 = blockIdx.x * 64;

    const float* are = Are + (size_t)b * strideA;
    const float* aim = Aim + (size_t)b * strideA;
    const float* ure = Ure + (size_t)b * d * rest + n0;
    const float* uim = Uim + (size_t)b * d * rest + n0;
    float*       cre = Cre + (size_t)b * d * rest + n0;
    float*       cim = Cim + (size_t)b * d * rest + n0;

    const int tid = threadIdx.x;
    const int tn4 = (tid & 15) * 4;     // frag cols tn4..tn4+3
    const int tm  = tid >> 4;           // frag rows tm*4..tm*4+3
    const int tm8 = tm * 8;             // dup-offset into A rows
    const int brr = tid >> 4;           // B loader k-row 0..15
    const int bc4 = (tid & 15) * 4;     // B loader col
    const int arr = tid >> 2;           // A loader m-row 0..63
    const int ac4 = (tid & 3) * 4;      // A loader k-col

    u64 T1[4][2], T2[4][2], T3[4][2];
#pragma unroll
    for (int i = 0; i < 4; i++)
#pragma unroll
        for (int c = 0; c < 2; c++) { T1[i][c] = 0ULL; T2[i][c] = 0ULL; T3[i][c] = 0ULL; }

    // prefetch first tile
    float4 pbr = *(const float4*)(ure + (size_t)brr * rest + bc4);
    float4 pbi = *(const float4*)(uim + (size_t)brr * rest + bc4);
    float4 par = *(const float4*)(are + (size_t)(m0 + arr) * d + ac4);
    float4 pai = *(const float4*)(aim + (size_t)(m0 + arr) * d + ac4);

    for (int kk = 0; kk < d; kk += 16) {
        *(float4*)&Bre[brr][bc4] = pbr;
        *(float4*)&Bim[brr][bc4] = pbi;
        {
            const float* pr = (const float*)&par;
            const float* pi = (const float*)&pai;
#pragma unroll
            for (int j = 0; j < 4; j++) {
                float vr = pr[j], vi = pi[j];
                *(float2*)&Adr[ac4 + j][2 * arr] = make_float2(vr, vr);
                *(float2*)&Adi[ac4 + j][2 * arr] = make_float2(vi, vi);
                float vs = vr + vi;
                *(float2*)&Ads[ac4 + j][2 * arr] = make_float2(vs, vs);
            }
        }
        __syncthreads();

        if (kk + 16 < d) {      // prefetch next tile (LDGs overlap compute)
            pbr = *(const float4*)(ure + (size_t)(kk + 16 + brr) * rest + bc4);
            pbi = *(const float4*)(uim + (size_t)(kk + 16 + brr) * rest + bc4);
            par = *(const float4*)(are + (size_t)(m0 + arr) * d + kk + 16 + ac4);
            pai = *(const float4*)(aim + (size_t)(m0 + arr) * d + kk + 16 + ac4);
        }

#pragma unroll
        for (int k = 0; k < 16; k++) {
            u64 br0, br1, bi0, bi1, bs0, bs1, a0, a1, a2, a3;
            lds2(br0, br1, &Bre[k][tn4]);
            lds2(bi0, bi1, &Bim[k][tn4]);
            add2(bs0, br0, bi0); add2(bs1, br1, bi1);

            lds2(a0, a1, &Adr[k][tm8]);
            lds2(a2, a3, &Adr[k][tm8 + 4]);
            fma2(T1[0][0], a0, br0); fma2(T1[0][1], a0, br1);
            fma2(T1[1][0], a1, br0); fma2(T1[1][1], a1, br1);
            fma2(T1[2][0], a2, br0); fma2(T1[2][1], a2, br1);
            fma2(T1[3][0], a3, br0); fma2(T1[3][1], a3, br1);

            lds2(a0, a1, &Adi[k][tm8]);
            lds2(a2, a3, &Adi[k][tm8 + 4]);
            fma2(T2[0][0], a0, bi0); fma2(T2[0][1], a0, bi1);
            fma2(T2[1][0], a1, bi0); fma2(T2[1][1], a1, bi1);
            fma2(T2[2][0], a2, bi0); fma2(T2[2][1], a2, bi1);
            fma2(T2[3][0], a3, bi0); fma2(T2[3][1], a3, bi1);

            lds2(a0, a1, &Ads[k][tm8]);
            lds2(a2, a3, &Ads[k][tm8 + 4]);
            fma2(T3[0][0], a0, bs0); fma2(T3[0][1], a0, bs1);
            fma2(T3[1][0], a1, bs0); fma2(T3[1][1], a1, bs1);
            fma2(T3[2][0], a2, bs0); fma2(T3[2][1], a2, bs1);
            fma2(T3[3][0], a3, bs0); fma2(T3[3][1], a3, bs1);
        }
        __syncthreads();
    }

#pragma unroll
    for (int i = 0; i < 4; i++) {
        int m = m0 + tm * 4 + i;
        float re[4], im_[4];
#pragma unroll
        for (int c = 0; c < 2; c++) {
            float t1l, t1h, t2l, t2h, t3l, t3h;
            unpack2(t1l, t1h, T1[i][c]);
            unpack2(t2l, t2h, T2[i][c]);
            unpack2(t3l, t3h, T3[i][c]);
            re[2 * c]      = t1l - t2l;
            re[2 * c + 1]  = t1h - t2h;
            im_[2 * c]     = t3l - t1l - t2l;
            im_[2 * c + 1] = t3h - t1h - t2h;
        }
        *(float4*)(cre + (size_t)m * rest + tn4) = make_float4(re[0], re[1], re[2], re[3]);
        *(float4*)(cim + (size_t)m * rest + tn4) = make_float4(im_[0], im_[1], im_[2], im_[3]);
    }
}

// ============ NT split-K: P[chunk][b] = L[b] * U[b]^T (K chunk) ============
// tile: BM=64, BN=64, BK=16; 256 threads; per-thread 4(M) x 4(N)
__global__ __launch_bounds__(256, 2)
void cgemm_nt(const float* __restrict__ Lre, const float* __restrict__ Lim,
              const float* __restrict__ Ure, const float* __restrict__ Uim,
              float* __restrict__ Pre, float* __restrict__ Pim,
              int d, int K, int KC)
{
    __shared__ __align__(16) float Adr[16][APAD], Adi[16][APAD], Ads[16][APAD];
    __shared__ __align__(16) float Bre[16][BPAD], Bim[16][BPAD];

    const int bz    = blockIdx.z;
    const int b     = bz & 7;
    const int chunk = bz >> 3;
    const int m0    = blockIdx.y * 64;
    const int n0    = blockIdx.x * 64;

    const float* lre = Lre + (size_t)b * d * K;
    const float* lim = Lim + (size_t)b * d * K;
    const float* ure = Ure + (size_t)b * d * K;
    const float* uim = Uim + (size_t)b * d * K;

    const int tid = threadIdx.x;
    const int tn4 = (tid & 15) * 4;
    const int tm  = tid >> 4;
    const int tm8 = tm * 8;
    const int lrr = tid >> 2;           // loader row 0..63 (both A and B)
    const int lc4 = (tid & 3) * 4;      // loader k-col

    u64 T1[4][2], T2[4][2], T3[4][2];
#pragma unroll
    for (int i = 0; i < 4; i++)
#pragma unroll
        for (int c = 0; c < 2; c++) { T1[i][c] = 0ULL; T2[i][c] = 0ULL; T3[i][c] = 0ULL; }

    const int kbeg = chunk * KC;
    const int kend = kbeg + KC;

    float4 par = *(const float4*)(lre + (size_t)(m0 + lrr) * K + kbeg + lc4);
    float4 pai = *(const float4*)(lim + (size_t)(m0 + lrr) * K + kbeg + lc4);
    float4 pbr = *(const float4*)(ure + (size_t)(n0 + lrr) * K + kbeg + lc4);
    float4 pbi = *(const float4*)(uim + (size_t)(n0 + lrr) * K + kbeg + lc4);

    for (int kk = kbeg; kk < kend; kk += 16) {
        {
            const float* pr = (const float*)&par;
            const float* pi = (const float*)&pai;
            const float* qr = (const float*)&pbr;
            const float* qi = (const float*)&pbi;
#pragma unroll
            for (int j = 0; j < 4; j++) {
                float vr = pr[j], vi = pi[j];
                *(float2*)&Adr[lc4 + j][2 * lrr] = make_float2(vr, vr);
                *(float2*)&Adi[lc4 + j][2 * lrr] = make_float2(vi, vi);
                float vs = vr + vi;
                *(float2*)&Ads[lc4 + j][2 * lrr] = make_float2(vs, vs);
                Bre[lc4 + j][lrr] = qr[j];
                Bim[lc4 + j][lrr] = qi[j];
            }
        }
        __syncthreads();

        if (kk + 16 < kend) {
            par = *(const float4*)(lre + (size_t)(m0 + lrr) * K + kk + 16 + lc4);
            pai = *(const float4*)(lim + (size_t)(m0 + lrr) * K + kk + 16 + lc4);
            pbr = *(const float4*)(ure + (size_t)(n0 + lrr) * K + kk + 16 + lc4);
            pbi = *(const float4*)(uim + (size_t)(n0 + lrr) * K + kk + 16 + lc4);
        }

#pragma unroll
        for (int k = 0; k < 16; k++) {
            u64 br0, br1, bi0, bi1, bs0, bs1, a0, a1, a2, a3;
            lds2(br0, br1, &Bre[k][tn4]);
            lds2(bi0, bi1, &Bim[k][tn4]);
            add2(bs0, br0, bi0); add2(bs1, br1, bi1);

            lds2(a0, a1, &Adr[k][tm8]);
            lds2(a2, a3, &Adr[k][tm8 + 4]);
            fma2(T1[0][0], a0, br0); fma2(T1[0][1], a0, br1);
            fma2(T1[1][0], a1, br0); fma2(T1[1][1], a1, br1);
            fma2(T1[2][0], a2, br0); fma2(T1[2][1], a2, br1);
            fma2(T1[3][0], a3, br0); fma2(T1[3][1], a3, br1);

            lds2(a0, a1, &Adi[k][tm8]);
            lds2(a2, a3, &Adi[k][tm8 + 4]);
            fma2(T2[0][0], a0, bi0); fma2(T2[0][1], a0, bi1);
            fma2(T2[1][0], a1, bi0); fma2(T2[1][1], a1, bi1);
            fma2(T2[2][0], a2, bi0); fma2(T2[2][1], a2, bi1);
            fma2(T2[3][0], a3, bi0); fma2(T2[3][1], a3, bi1);

            lds2(a0, a1, &Ads[k][tm8]);
            lds2(a2, a3, &Ads[k][tm8 + 4]);
            fma2(T3[0][0], a0, bs0); fma2(T3[0][1], a0, bs1);
            fma2(T3[1][0], a1, bs0); fma2(T3[1][1], a1, bs1);
            fma2(T3[2][0], a2, bs0); fma2(T3[2][1], a2, bs1);
            fma2(T3[3][0], a3, bs0); fma2(T3[3][1], a3, bs1);
        }
        __syncthreads();
    }

    size_t off = (size_t)(chunk * BATCH + b) * d * d;
#pragma unroll
    for (int i = 0; i < 4; i++) {
        int m = m0 + tm * 4 + i;
        float re[4], im_[4];
#pragma unroll
        for (int c = 0; c < 2; c++) {
            float t1l, t1h, t2l, t2h, t3l, t3h;
            unpack2(t1l, t1h, T1[i][c]);
            unpack2(t2l, t2h, T2[i][c]);
            unpack2(t3l, t3h, T3[i][c]);
            re[2 * c]      = t1l - t2l;
            re[2 * c + 1]  = t1h - t2h;
            im_[2 * c]     = t3l - t1l - t2l;
            im_[2 * c + 1] = t3h - t1h - t2h;
        }
        *(float4*)(Pre + off + (size_t)m * d + n0 + tn4) = make_float4(re[0], re[1], re[2], re[3]);
        *(float4*)(Pim + off + (size_t)m * d + n0 + tn4) = make_float4(im_[0], im_[1], im_[2], im_[3]);
    }
}

// ---------------- fused split-K reduce + softmax(|s|/scale)*phase ---------
__global__ void softmax_fused(const float* __restrict__ Pre, const float* __restrict__ Pim,
                              float* __restrict__ Mre, float* __restrict__ Mim,
                              int d, int n, int nchunks,
                              const float* __restrict__ logtau, float sfac)
{
    const int row = blockIdx.x;
    const int j   = threadIdx.x;
    const int idx = row * d + j;

    float sr = 0.f, si = 0.f;
    for (int c = 0; c < nchunks; c++) {
        sr += Pre[(size_t)c * n + idx];
        si += Pim[(size_t)c * n + idx];
    }
    const float mag = sqrtf(sr * sr + si * si);

    const float tau   = fmaxf(expf(logtau[0]), 1e-8f);
    const float scale = tau * sfac;
    const float logit = mag / scale;

    __shared__ float wred[4];
    __shared__ float wsum[4];
    const int warp = j >> 5, lane = j & 31, nw = d >> 5;

    float v = logit;
#pragma unroll
    for (int o = 16; o > 0; o >>= 1) v = fmaxf(v, __shfl_xor_sync(0xffffffffu, v, o));
    if (lane == 0) wred[warp] = v;
    __syncthreads();
    float mx = wred[0];
    for (int w = 1; w < nw; w++) mx = fmaxf(mx, wred[w]);

    const float e = expf(logit - mx);
    float s_ = e;
#pragma unroll
    for (int o = 16; o > 0; o >>= 1) s_ += __shfl_xor_sync(0xffffffffu, s_, o);
    if (lane == 0) wsum[warp] = s_;
    __syncthreads();
    float tot = 0.f;
    for (int w = 0; w < nw; w++) tot += wsum[w];

    const float routing = e / tot;
    float pr, pi;
    if (mag > 1e-8f) { pr = sr / mag; pi = si / mag; }
    else             { pr = 1.f;      pi = 0.f; }
    Mre[(size_t)row * d + j] = routing * pr;
    Mim[(size_t)row * d + j] = routing * pi;
}

// ---------------- mode-1 permute (float4): swap the two 128-axes ----------
__global__ void perm_swap01(const float4* __restrict__ s4re, const float4* __restrict__ s4im,
                            float4* __restrict__ d4re, float4* __restrict__ d4im)
{
    int t = blockIdx.x * 256 + threadIdx.x;     // < NTOT/4 = 2097152
    int k4 = t & 15;
    int q  = (t >> 4) & 127;
    int p  = (t >> 11) & 127;
    int b  = t >> 18;
    int src = ((((b << 7) | q) << 7) | p) << 4 | k4;
    d4re[t] = s4re[src];
    d4im[t] = s4im[src];
}

// ---------------- batched 2D transpose: dst[b][c][r] = src[b][r][c] -------
__global__ void perm_transpose(const float* __restrict__ sre, const float* __restrict__ sim,
                               float* __restrict__ dre, float* __restrict__ dim_,
                               int R, int C)
{
    __shared__ float tre[32][33], tim[32][33];
    const int b  = blockIdx.z;
    const int r0 = blockIdx.y * 32;
    const int c0 = blockIdx.x * 32;
    const float* sr_ = sre + (size_t)b * R * C;
    const float* si_ = sim + (size_t)b * R * C;
    float*       dr_ = dre + (size_t)b * R * C;
    float*       di_ = dim_ + (size_t)b * R * C;
    const int x = threadIdx.x, y = threadIdx.y;    // 32 x 8
#pragma unroll
    for (int i = y; i < 32; i += 8) {
        tre[i][x] = sr_[(size_t)(r0 + i) * C + c0 + x];
        tim[i][x] = si_[(size_t)(r0 + i) * C + c0 + x];
    }
    __syncthreads();
#pragma unroll
    for (int i = y; i < 32; i += 8) {
        dr_[(size_t)(c0 + i) * R + r0 + x] = tre[x][i];
        di_[(size_t)(c0 + i) * R + r0 + x] = tim[x][i];
    }
}

// --------------------------------------------------------------------------
extern "C" void kernel_launch(void* const* d_in, const int* in_sizes, int n_in,
                              void* d_out, int out_size)
{
    (void)in_sizes; (void)n_in; (void)out_size;
    const float* xre  = (const float*)d_in[0];
    const float* xim  = (const float*)d_in[1];
    const float* w0re = (const float*)d_in[2];
    const float* w0im = (const float*)d_in[3];
    const float* w1re = (const float*)d_in[4];
    const float* w1im = (const float*)d_in[5];
    const float* w2re = (const float*)d_in[6];
    const float* w2im = (const float*)d_in[7];
    const float* ltau = (const float*)d_in[8];
    float* out_re = (float*)d_out;
    float* out_im = out_re + (size_t)NTOT;

    float *s_re, *s_im, *u_re, *u_im, *l_re, *l_im, *p_re, *p_im, *m_re, *m_im;
    cudaGetSymbolAddress((void**)&s_re,  g_s_re);
    cudaGetSymbolAddress((void**)&s_im,  g_s_im);
    cudaGetSymbolAddress((void**)&u_re,  g_u_re);
    cudaGetSymbolAddress((void**)&u_im,  g_u_im);
    cudaGetSymbolAddress((void**)&l_re,  g_l_re);
    cudaGetSymbolAddress((void**)&l_im,  g_l_im);
    cudaGetSymbolAddress((void**)&p_re,  g_p_re);
    cudaGetSymbolAddress((void**)&p_im,  g_p_im);
    cudaGetSymbolAddress((void**)&m_re,  g_m_re);
    cudaGetSymbolAddress((void**)&m_im,  g_m_im);

    // ---------------- Mode 0: d=128, rest=8192 (unfold = identity) --------
    {
        const int d = 128, rest = 8192;
        dim3 g1(rest / 64, d / 64, BATCH);
        cgemm_nn<<<g1, 256>>>(w0re, w0im, 0, xre, xim, l_re, l_im, d, rest);

        const int NC = 32, KC = rest / NC;        // 256
        dim3 g2(d / 64, d / 64, BATCH * NC);
        cgemm_nt<<<g2, 256>>>(l_re, l_im, xre, xim, p_re, p_im, d, rest, KC);

        const int n = BATCH * d * d;
        softmax_fused<<<BATCH * d, d>>>(p_re, p_im, m_re, m_im, d, n, NC, ltau,
                                        sqrtf((float)SS / (float)d));
        cgemm_nn<<<g1, 256>>>(m_re, m_im, d * d, xre, xim, s_re, s_im, d, rest);
    }

    // ---------------- Mode 1: d=128, rest=8192 ----------------------------
    {
        const int d = 128, rest = 8192;
        perm_swap01<<<(NTOT / 4) / 256, 256>>>((const float4*)s_re, (const float4*)s_im,
                                               (float4*)u_re, (float4*)u_im);

        dim3 g1(rest / 64, d / 64, BATCH);
        cgemm_nn<<<g1, 256>>>(w1re, w1im, 0, u_re, u_im, l_re, l_im, d, rest);

        const int NC = 32, KC = rest / NC;
        dim3 g2(d / 64, d / 64, BATCH * NC);
        cgemm_nt<<<g2, 256>>>(l_re, l_im, u_re, u_im, p_re, p_im, d, rest, KC);

        const int n = BATCH * d * d;
        softmax_fused<<<BATCH * d, d>>>(p_re, p_im, m_re, m_im, d, n, NC, ltau,
                                        sqrtf((float)SS / (float)d));
        cgemm_nn<<<g1, 256>>>(m_re, m_im, d * d, u_re, u_im, l_re, l_im, d, rest);
        perm_swap01<<<(NTOT / 4) / 256, 256>>>((const float4*)l_re, (const float4*)l_im,
                                               (float4*)s_re, (float4*)s_im);
    }

    // ---------------- Mode 2: d=64, rest=16384 ----------------------------
    {
        const int d = 64, rest = 16384;
        // unfold: u[b, k, p] = s[b, p, k]   (src R=16384, C=64)
        dim3 gt(64 / 32, 16384 / 32, BATCH);
        perm_transpose<<<gt, dim3(32, 8)>>>(s_re, s_im, u_re, u_im, 16384, 64);

        dim3 g1(rest / 64, d / 64, BATCH);
        cgemm_nn<<<g1, 256>>>(w2re, w2im, 0, u_re, u_im, l_re, l_im, d, rest);

        const int NC = 64, KC = rest / NC;        // 256
        dim3 g2(d / 64, d / 64, BATCH * NC);
        cgemm_nt<<<g2, 256>>>(l_re, l_im, u_re, u_im, p_re, p_im, d, rest, KC);

        const int n = BATCH * d * d;
        softmax_fused<<<BATCH * d, d>>>(p_re, p_im, m_re, m_im, d, n, NC, ltau,
                                        sqrtf((float)SS / (float)d));
        cgemm_nn<<<g1, 256>>>(m_re, m_im, d * d, u_re, u_im, l_re, l_im, d, rest);

        // fold: out[b, p, k] = mixed[b, k, p]   (src R=64, C=16384) -> d_out
        dim3 gt2(16384 / 32, 64 / 32, BATCH);
        perm_transpose<<<gt2, dim3(32, 8)>>>(l_re, l_im, out_re, out_im, 64, 16384);
    }
}

// round 9
// speedup vs baseline: 1.2183x; 1.2113x over previous
#include <cuda_runtime.h>
#include <math.h>

#define BATCH 8
#define SS 1048576              // 128*128*64
#define NTOT (BATCH * SS)       // 8388608 per component

// ---------------- scratch (device globals; no allocation) ----------------
__device__ float g_s_re[NTOT];
__device__ float g_s_im[NTOT];
__device__ float g_u_re[NTOT];
__device__ float g_u_im[NTOT];
__device__ float g_l_re[NTOT];
__device__ float g_l_im[NTOT];
__device__ float g_p_re[4194304];   // split-K partials (NC*B*d*d max)
__device__ float g_p_im[4194304];
__device__ float g_m_re[131072];    // routing matrix (B*d*d max)
__device__ float g_m_im[131072];

typedef unsigned long long u64;

// ---------------- f32x2 packed helpers ------------------------------------
__device__ __forceinline__ u64 pack2(float x) {
    unsigned xi = __float_as_uint(x);
    u64 r;
    asm("mov.b64 %0, {%1,%2};" : "=l"(r) : "r"(xi), "r"(xi));
    return r;
}
__device__ __forceinline__ void fma2(u64& d, u64 a, u64 b) {
    asm("fma.rn.f32x2 %0, %1, %2, %3;" : "=l"(d) : "l"(a), "l"(b), "l"(d));
}
__device__ __forceinline__ void add2(u64& d, u64 a, u64 b) {
    asm("add.rn.f32x2 %0, %1, %2;" : "=l"(d) : "l"(a), "l"(b));
}
__device__ __forceinline__ void lds2(u64& lo, u64& hi, const float* p) {
    unsigned a = (unsigned)__cvta_generic_to_shared(p);
    asm volatile("ld.shared.v2.b64 {%0,%1}, [%2];" : "=l"(lo), "=l"(hi) : "r"(a));
}
__device__ __forceinline__ void unpack2(float& lo, float& hi, u64 v) {
    unsigned a, b;
    asm("mov.b64 {%0,%1}, %2;" : "=r"(a), "=r"(b) : "l"(v));
    lo = __uint_as_float(a); hi = __uint_as_float(b);
}

#define BKT 16
#define SPAD 68                 // padded smem row (16B-aligned, conflict-light)

// mainloop body shared by NN and NT: 4 LDS + 6 ADD2 + 24 FMA2 per k
#define KSTEP(Asr, Asi, Bsr, Bsi, k)                                         \
    {                                                                        \
        u64 br0, br1, bi0, bi1, bs0, bs1;                                    \
        lds2(br0, br1, &Bsr[k][tn4]);                                        \
        lds2(bi0, bi1, &Bsi[k][tn4]);                                        \
        add2(bs0, br0, bi0); add2(bs1, br1, bi1);                            \
        float4 arv = *(const float4*)&Asr[k][tm4];                           \
        float4 aiv = *(const float4*)&Asi[k][tm4];                           \
        u64 a0 = pack2(arv.x), a1 = pack2(arv.y);                            \
        u64 a2 = pack2(arv.z), a3 = pack2(arv.w);                            \
        u64 i0 = pack2(aiv.x), i1 = pack2(aiv.y);                            \
        u64 i2 = pack2(aiv.z), i3 = pack2(aiv.w);                            \
        fma2(T1[0][0], a0, br0); fma2(T1[0][1], a0, br1);                    \
        fma2(T1[1][0], a1, br0); fma2(T1[1][1], a1, br1);                    \
        fma2(T1[2][0], a2, br0); fma2(T1[2][1], a2, br1);                    \
        fma2(T1[3][0], a3, br0); fma2(T1[3][1], a3, br1);                    \
        fma2(T2[0][0], i0, bi0); fma2(T2[0][1], i0, bi1);                    \
        fma2(T2[1][0], i1, bi0); fma2(T2[1][1], i1, bi1);                    \
        fma2(T2[2][0], i2, bi0); fma2(T2[2][1], i2, bi1);                    \
        fma2(T2[3][0], i3, bi0); fma2(T2[3][1], i3, bi1);                    \
        add2(a0, a0, i0); add2(a1, a1, i1);                                  \
        add2(a2, a2, i2); add2(a3, a3, i3);                                  \
        fma2(T3[0][0], a0, bs0); fma2(T3[0][1], a0, bs1);                    \
        fma2(T3[1][0], a1, bs0); fma2(T3[1][1], a1, bs1);                    \
        fma2(T3[2][0], a2, bs0); fma2(T3[2][1], a2, bs1);                    \
        fma2(T3[3][0], a3, bs0); fma2(T3[3][1], a3, bs1);                    \
    }

// ======================= NN kernel: C[b] = A(b?) * U[b] ====================
// tile: BM=64, BN=64, BK=16; 256 threads; per-thread 4(M) x 4(N); 2 CTAs/SM
// Karatsuba: T1=ar*br, T2=ai*bi, T3=(ar+ai)(br+bi); cr=T1-T2, ci=T3-T1-T2
// Sum components computed in registers (smem holds only re/im tiles).
__global__ __launch_bounds__(256, 2)
void cgemm_nn(const float* __restrict__ Are, const float* __restrict__ Aim, int strideA,
              const float* __restrict__ Ure, const float* __restrict__ Uim,
              float* __restrict__ Cre, float* __restrict__ Cim,
              int d, int rest)
{
    __shared__ __align__(16) float As_re[BKT][SPAD], As_im[BKT][SPAD];
    __shared__ __align__(16) float Bs_re[BKT][SPAD], Bs_im[BKT][SPAD];

    const int b  = blockIdx.z;
    const int m0 = blockIdx.y * 64;
    const int n0 = blockIdx.x * 64;

    const float* are = Are + (size_t)b * strideA;
    const float* aim = Aim + (size_t)b * strideA;
    const float* ure = Ure + (size_t)b * d * rest + n0;
    const float* uim = Uim + (size_t)b * d * rest + n0;
    float*       cre = Cre + (size_t)b * d * rest + n0;
    float*       cim = Cim + (size_t)b * d * rest + n0;

    const int tid = threadIdx.x;
    const int tn4 = (tid & 15) * 4;     // frag cols
    const int tm4 = (tid >> 4) * 4;     // frag rows
    const int arow = tid >> 2;          // A loader m-row 0..63
    const int ac4  = (tid & 3) * 4;     // A loader k-col
    const int ukr  = tid >> 4;          // B loader k-row 0..15
    const int un4  = (tid & 15) * 4;    // B loader col

    u64 T1[4][2], T2[4][2], T3[4][2];
#pragma unroll
    for (int i = 0; i < 4; i++)
#pragma unroll
        for (int c = 0; c < 2; c++) { T1[i][c] = 0ULL; T2[i][c] = 0ULL; T3[i][c] = 0ULL; }

    // prefetch first tile
    float4 pa_r = *(const float4*)(are + (size_t)(m0 + arow) * d + ac4);
    float4 pa_i = *(const float4*)(aim + (size_t)(m0 + arow) * d + ac4);
    float4 pb_r = *(const float4*)(ure + (size_t)ukr * rest + un4);
    float4 pb_i = *(const float4*)(uim + (size_t)ukr * rest + un4);

    for (int kk = 0; kk < d; kk += BKT) {
        As_re[ac4 + 0][arow] = pa_r.x; As_re[ac4 + 1][arow] = pa_r.y;
        As_re[ac4 + 2][arow] = pa_r.z; As_re[ac4 + 3][arow] = pa_r.w;
        As_im[ac4 + 0][arow] = pa_i.x; As_im[ac4 + 1][arow] = pa_i.y;
        As_im[ac4 + 2][arow] = pa_i.z; As_im[ac4 + 3][arow] = pa_i.w;
        *(float4*)&Bs_re[ukr][un4] = pb_r;
        *(float4*)&Bs_im[ukr][un4] = pb_i;
        __syncthreads();

        if (kk + BKT < d) {     // prefetch next tile (LDGs overlap compute)
            pa_r = *(const float4*)(are + (size_t)(m0 + arow) * d + kk + BKT + ac4);
            pa_i = *(const float4*)(aim + (size_t)(m0 + arow) * d + kk + BKT + ac4);
            pb_r = *(const float4*)(ure + (size_t)(kk + BKT + ukr) * rest + un4);
            pb_i = *(const float4*)(uim + (size_t)(kk + BKT + ukr) * rest + un4);
        }

#pragma unroll
        for (int k = 0; k < BKT; k++) KSTEP(As_re, As_im, Bs_re, Bs_im, k)
        __syncthreads();
    }

#pragma unroll
    for (int i = 0; i < 4; i++) {
        int m = m0 + tm4 + i;
        float re[4], im_[4];
#pragma unroll
        for (int c = 0; c < 2; c++) {
            float t1l, t1h, t2l, t2h, t3l, t3h;
            unpack2(t1l, t1h, T1[i][c]);
            unpack2(t2l, t2h, T2[i][c]);
            unpack2(t3l, t3h, T3[i][c]);
            re[2 * c]      = t1l - t2l;
            re[2 * c + 1]  = t1h - t2h;
            im_[2 * c]     = t3l - t1l - t2l;
            im_[2 * c + 1] = t3h - t1h - t2h;
        }
        *(float4*)(cre + (size_t)m * rest + tn4) = make_float4(re[0], re[1], re[2], re[3]);
        *(float4*)(cim + (size_t)m * rest + tn4) = make_float4(im_[0], im_[1], im_[2], im_[3]);
    }
}

// ============ NT split-K: P[chunk][b] = L[b] * U[b]^T (K chunk) ============
// tile: BM=64, BN=64, BK=16; 256 threads; per-thread 4(M) x 4(N)
__global__ __launch_bounds__(256, 2)
void cgemm_nt(const float* __restrict__ Lre, const float* __restrict__ Lim,
              const float* __restrict__ Ure, const float* __restrict__ Uim,
              float* __restrict__ Pre, float* __restrict__ Pim,
              int d, int K, int KC)
{
    __shared__ __align__(16) float As_re[BKT][SPAD], As_im[BKT][SPAD];
    __shared__ __align__(16) float Bs_re[BKT][SPAD], Bs_im[BKT][SPAD];

    const int bz    = blockIdx.z;
    const int b     = bz & 7;
    const int chunk = bz >> 3;
    const int m0    = blockIdx.y * 64;
    const int n0    = blockIdx.x * 64;

    const float* lre = Lre + (size_t)b * d * K;
    const float* lim = Lim + (size_t)b * d * K;
    const float* ure = Ure + (size_t)b * d * K;
    const float* uim = Uim + (size_t)b * d * K;

    const int tid = threadIdx.x;
    const int tn4 = (tid & 15) * 4;
    const int tm4 = (tid >> 4) * 4;
    const int lrr = tid >> 2;           // loader row 0..63 (both A and B)
    const int lc4 = (tid & 3) * 4;      // loader k-col

    u64 T1[4][2], T2[4][2], T3[4][2];
#pragma unroll
    for (int i = 0; i < 4; i++)
#pragma unroll
        for (int c = 0; c < 2; c++) { T1[i][c] = 0ULL; T2[i][c] = 0ULL; T3[i][c] = 0ULL; }

    const int kbeg = chunk * KC;
    const int kend = kbeg + KC;

    float4 par = *(const float4*)(lre + (size_t)(m0 + lrr) * K + kbeg + lc4);
    float4 pai = *(const float4*)(lim + (size_t)(m0 + lrr) * K + kbeg + lc4);
    float4 pbr = *(const float4*)(ure + (size_t)(n0 + lrr) * K + kbeg + lc4);
    float4 pbi = *(const float4*)(uim + (size_t)(n0 + lrr) * K + kbeg + lc4);

    for (int kk = kbeg; kk < kend; kk += BKT) {
        As_re[lc4 + 0][lrr] = par.x; As_re[lc4 + 1][lrr] = par.y;
        As_re[lc4 + 2][lrr] = par.z; As_re[lc4 + 3][lrr] = par.w;
        As_im[lc4 + 0][lrr] = pai.x; As_im[lc4 + 1][lrr] = pai.y;
        As_im[lc4 + 2][lrr] = pai.z; As_im[lc4 + 3][lrr] = pai.w;
        Bs_re[lc4 + 0][lrr] = pbr.x; Bs_re[lc4 + 1][lrr] = pbr.y;
        Bs_re[lc4 + 2][lrr] = pbr.z; Bs_re[lc4 + 3][lrr] = pbr.w;
        Bs_im[lc4 + 0][lrr] = pbi.x; Bs_im[lc4 + 1][lrr] = pbi.y;
        Bs_im[lc4 + 2][lrr] = pbi.z; Bs_im[lc4 + 3][lrr] = pbi.w;
        __syncthreads();

        if (kk + BKT < kend) {
            par = *(const float4*)(lre + (size_t)(m0 + lrr) * K + kk + BKT + lc4);
            pai = *(const float4*)(lim + (size_t)(m0 + lrr) * K + kk + BKT + lc4);
            pbr = *(const float4*)(ure + (size_t)(n0 + lrr) * K + kk + BKT + lc4);
            pbi = *(const float4*)(uim + (size_t)(n0 + lrr) * K + kk + BKT + lc4);
        }

#pragma unroll
        for (int k = 0; k < BKT; k++) KSTEP(As_re, As_im, Bs_re, Bs_im, k)
        __syncthreads();
    }

    size_t off = (size_t)(chunk * BATCH + b) * d * d;
#pragma unroll
    for (int i = 0; i < 4; i++) {
        int m = m0 + tm4 + i;
        float re[4], im_[4];
#pragma unroll
        for (int c = 0; c < 2; c++) {
            float t1l, t1h, t2l, t2h, t3l, t3h;
            unpack2(t1l, t1h, T1[i][c]);
            unpack2(t2l, t2h, T2[i][c]);
            unpack2(t3l, t3h, T3[i][c]);
            re[2 * c]      = t1l - t2l;
            re[2 * c + 1]  = t1h - t2h;
            im_[2 * c]     = t3l - t1l - t2l;
            im_[2 * c + 1] = t3h - t1h - t2h;
        }
        *(float4*)(Pre + off + (size_t)m * d + n0 + tn4) = make_float4(re[0], re[1], re[2], re[3]);
        *(float4*)(Pim + off + (size_t)m * d + n0 + tn4) = make_float4(im_[0], im_[1], im_[2], im_[3]);
    }
}

// ---------------- fused split-K reduce + softmax(|s|/scale)*phase ---------
__global__ void softmax_fused(const float* __restrict__ Pre, const float* __restrict__ Pim,
                              float* __restrict__ Mre, float* __restrict__ Mim,
                              int d, int n, int nchunks,
                              const float* __restrict__ logtau, float sfac)
{
    const int row = blockIdx.x;
    const int j   = threadIdx.x;
    const int idx = row * d + j;

    float sr = 0.f, si = 0.f;
    for (int c = 0; c < nchunks; c++) {
        sr += Pre[(size_t)c * n + idx];
        si += Pim[(size_t)c * n + idx];
    }
    const float mag = sqrtf(sr * sr + si * si);

    const float tau   = fmaxf(expf(logtau[0]), 1e-8f);
    const float scale = tau * sfac;
    const float logit = mag / scale;

    __shared__ float wred[4];
    __shared__ float wsum[4];
    const int warp = j >> 5, lane = j & 31, nw = d >> 5;

    float v = logit;
#pragma unroll
    for (int o = 16; o > 0; o >>= 1) v = fmaxf(v, __shfl_xor_sync(0xffffffffu, v, o));
    if (lane == 0) wred[warp] = v;
    __syncthreads();
    float mx = wred[0];
    for (int w = 1; w < nw; w++) mx = fmaxf(mx, wred[w]);

    const float e = expf(logit - mx);
    float s_ = e;
#pragma unroll
    for (int o = 16; o > 0; o >>= 1) s_ += __shfl_xor_sync(0xffffffffu, s_, o);
    if (lane == 0) wsum[warp] = s_;
    __syncthreads();
    float tot = 0.f;
    for (int w = 0; w < nw; w++) tot += wsum[w];

    const float routing = e / tot;
    float pr, pi;
    if (mag > 1e-8f) { pr = sr / mag; pi = si / mag; }
    else             { pr = 1.f;      pi = 0.f; }
    Mre[(size_t)row * d + j] = routing * pr;
    Mim[(size_t)row * d + j] = routing * pi;
}

// ---------------- mode-1 permute (float4): swap the two 128-axes ----------
__global__ void perm_swap01(const float4* __restrict__ s4re, const float4* __restrict__ s4im,
                            float4* __restrict__ d4re, float4* __restrict__ d4im)
{
    int t = blockIdx.x * 256 + threadIdx.x;     // < NTOT/4 = 2097152
    int k4 = t & 15;
    int q  = (t >> 4) & 127;
    int p  = (t >> 11) & 127;
    int b  = t >> 18;
    int src = ((((b << 7) | q) << 7) | p) << 4 | k4;
    d4re[t] = s4re[src];
    d4im[t] = s4im[src];
}

// ---------------- batched 2D transpose: dst[b][c][r] = src[b][r][c] -------
__global__ void perm_transpose(const float* __restrict__ sre, const float* __restrict__ sim,
                               float* __restrict__ dre, float* __restrict__ dim_,
                               int R, int C)
{
    __shared__ float tre[32][33], tim[32][33];
    const int b  = blockIdx.z;
    const int r0 = blockIdx.y * 32;
    const int c0 = blockIdx.x * 32;
    const float* sr_ = sre + (size_t)b * R * C;
    const float* si_ = sim + (size_t)b * R * C;
    float*       dr_ = dre + (size_t)b * R * C;
    float*       di_ = dim_ + (size_t)b * R * C;
    const int x = threadIdx.x, y = threadIdx.y;    // 32 x 8
#pragma unroll
    for (int i = y; i < 32; i += 8) {
        tre[i][x] = sr_[(size_t)(r0 + i) * C + c0 + x];
        tim[i][x] = si_[(size_t)(r0 + i) * C + c0 + x];
    }
    __syncthreads();
#pragma unroll
    for (int i = y; i < 32; i += 8) {
        dr_[(size_t)(c0 + i) * R + r0 + x] = tre[x][i];
        di_[(size_t)(c0 + i) * R + r0 + x] = tim[x][i];
    }
}

// --------------------------------------------------------------------------
extern "C" void kernel_launch(void* const* d_in, const int* in_sizes, int n_in,
                              void* d_out, int out_size)
{
    (void)in_sizes; (void)n_in; (void)out_size;
    const float* xre  = (const float*)d_in[0];
    const float* xim  = (const float*)d_in[1];
    const float* w0re = (const float*)d_in[2];
    const float* w0im = (const float*)d_in[3];
    const float* w1re = (const float*)d_in[4];
    const float* w1im = (const float*)d_in[5];
    const float* w2re = (const float*)d_in[6];
    const float* w2im = (const float*)d_in[7];
    const float* ltau = (const float*)d_in[8];
    float* out_re = (float*)d_out;
    float* out_im = out_re + (size_t)NTOT;

    float *s_re, *s_im, *u_re, *u_im, *l_re, *l_im, *p_re, *p_im, *m_re, *m_im;
    cudaGetSymbolAddress((void**)&s_re,  g_s_re);
    cudaGetSymbolAddress((void**)&s_im,  g_s_im);
    cudaGetSymbolAddress((void**)&u_re,  g_u_re);
    cudaGetSymbolAddress((void**)&u_im,  g_u_im);
    cudaGetSymbolAddress((void**)&l_re,  g_l_re);
    cudaGetSymbolAddress((void**)&l_im,  g_l_im);
    cudaGetSymbolAddress((void**)&p_re,  g_p_re);
    cudaGetSymbolAddress((void**)&p_im,  g_p_im);
    cudaGetSymbolAddress((void**)&m_re,  g_m_re);
    cudaGetSymbolAddress((void**)&m_im,  g_m_im);

    // ---------------- Mode 0: d=128, rest=8192 (unfold = identity) --------
    {
        const int d = 128, rest = 8192;
        dim3 g1(rest / 64, d / 64, BATCH);
        cgemm_nn<<<g1, 256>>>(w0re, w0im, 0, xre, xim, l_re, l_im, d, rest);

        const int NC = 32, KC = rest / NC;        // 256
        dim3 g2(d / 64, d / 64, BATCH * NC);
        cgemm_nt<<<g2, 256>>>(l_re, l_im, xre, xim, p_re, p_im, d, rest, KC);

        const int n = BATCH * d * d;
        softmax_fused<<<BATCH * d, d>>>(p_re, p_im, m_re, m_im, d, n, NC, ltau,
                                        sqrtf((float)SS / (float)d));
        cgemm_nn<<<g1, 256>>>(m_re, m_im, d * d, xre, xim, s_re, s_im, d, rest);
    }

    // ---------------- Mode 1: d=128, rest=8192 ----------------------------
    {
        const int d = 128, rest = 8192;
        perm_swap01<<<(NTOT / 4) / 256, 256>>>((const float4*)s_re, (const float4*)s_im,
                                               (float4*)u_re, (float4*)u_im);

        dim3 g1(rest / 64, d / 64, BATCH);
        cgemm_nn<<<g1, 256>>>(w1re, w1im, 0, u_re, u_im, l_re, l_im, d, rest);

        const int NC = 32, KC = rest / NC;
        dim3 g2(d / 64, d / 64, BATCH * NC);
        cgemm_nt<<<g2, 256>>>(l_re, l_im, u_re, u_im, p_re, p_im, d, rest, KC);

        const int n = BATCH * d * d;
        softmax_fused<<<BATCH * d, d>>>(p_re, p_im, m_re, m_im, d, n, NC, ltau,
                                        sqrtf((float)SS / (float)d));
        cgemm_nn<<<g1, 256>>>(m_re, m_im, d * d, u_re, u_im, l_re, l_im, d, rest);
        perm_swap01<<<(NTOT / 4) / 256, 256>>>((const float4*)l_re, (const float4*)l_im,
                                               (float4*)s_re, (float4*)s_im);
    }

    // ---------------- Mode 2: d=64, rest=16384 ----------------------------
    {
        const int d = 64, rest = 16384;
        // unfold: u[b, k, p] = s[b, p, k]   (src R=16384, C=64)
        dim3 gt(64 / 32, 16384 / 32, BATCH);
        perm_transpose<<<gt, dim3(32, 8)>>>(s_re, s_im, u_re, u_im, 16384, 64);

        dim3 g1(rest / 64, d / 64, BATCH);
        cgemm_nn<<<g1, 256>>>(w2re, w2im, 0, u_re, u_im, l_re, l_im, d, rest);

        const int NC = 64, KC = rest / NC;        // 256
        dim3 g2(d / 64, d / 64, BATCH * NC);
        cgemm_nt<<<g2, 256>>>(l_re, l_im, u_re, u_im, p_re, p_im, d, rest, KC);

        const int n = BATCH * d * d;
        softmax_fused<<<BATCH * d, d>>>(p_re, p_im, m_re, m_im, d, n, NC, ltau,
                                        sqrtf((float)SS / (float)d));
        cgemm_nn<<<g1, 256>>>(m_re, m_im, d * d, u_re, u_im, l_re, l_im, d, rest);

        // fold: out[b, p, k] = mixed[b, k, p]   (src R=64, C=16384) -> d_out
        dim3 gt2(16384 / 32, 64 / 32, BATCH);
        perm_transpose<<<gt2, dim3(32, 8)>>>(l_re, l_im, out_re, out_im, 64, 16384);
    }
}

// round 10
// speedup vs baseline: 1.2347x; 1.0134x over previous
#include <cuda_runtime.h>
#include <math.h>

#define BATCH 8
#define SS 1048576              // 128*128*64
#define NTOT (BATCH * SS)       // 8388608 per component

// ---------------- scratch (device globals; no allocation) ----------------
__device__ float g_s_re[NTOT];
__device__ float g_s_im[NTOT];
__device__ float g_u_re[NTOT];
__device__ float g_u_im[NTOT];
__device__ float g_l_re[NTOT];
__device__ float g_l_im[NTOT];
__device__ float g_p_re[4194304];   // split-K partials (NC*B*d*d max)
__device__ float g_p_im[4194304];
__device__ float g_m_re[131072];    // routing matrix (B*d*d max)
__device__ float g_m_im[131072];

typedef unsigned long long u64;

// ---------------- f32x2 packed helpers ------------------------------------
__device__ __forceinline__ u64 pack2(float x) {
    unsigned xi = __float_as_uint(x);
    u64 r;
    asm("mov.b64 %0, {%1,%2};" : "=l"(r) : "r"(xi), "r"(xi));
    return r;
}
__device__ __forceinline__ void fma2(u64& d, u64 a, u64 b) {
    asm("fma.rn.f32x2 %0, %1, %2, %3;" : "=l"(d) : "l"(a), "l"(b), "l"(d));
}
__device__ __forceinline__ void add2(u64& d, u64 a, u64 b) {
    asm("add.rn.f32x2 %0, %1, %2;" : "=l"(d) : "l"(a), "l"(b));
}
__device__ __forceinline__ void lds2(u64& lo, u64& hi, const float* p) {
    unsigned a = (unsigned)__cvta_generic_to_shared(p);
    asm volatile("ld.shared.v2.b64 {%0,%1}, [%2];" : "=l"(lo), "=l"(hi) : "r"(a));
}
__device__ __forceinline__ void unpack2(float& lo, float& hi, u64 v) {
    unsigned a, b;
    asm("mov.b64 {%0,%1}, %2;" : "=r"(a), "=r"(b) : "l"(v));
    lo = __uint_as_float(a); hi = __uint_as_float(b);
}

#define BKT 16
#define SPAD 68                 // padded smem row (16B-aligned, conflict-light)

// mainloop body shared by NN and NT: 4 LDS + 6 ADD2 + 24 FMA2 per k
#define KSTEP(Asr, Asi, Bsr, Bsi, k)                                         \
    {                                                                        \
        u64 br0, br1, bi0, bi1, bs0, bs1;                                    \
        lds2(br0, br1, &Bsr[k][tn4]);                                        \
        lds2(bi0, bi1, &Bsi[k][tn4]);                                        \
        add2(bs0, br0, bi0); add2(bs1, br1, bi1);                            \
        float4 arv = *(const float4*)&Asr[k][tm4];                           \
        float4 aiv = *(const float4*)&Asi[k][tm4];                           \
        u64 a0 = pack2(arv.x), a1 = pack2(arv.y);                            \
        u64 a2 = pack2(arv.z), a3 = pack2(arv.w);                            \
        u64 i0 = pack2(aiv.x), i1 = pack2(aiv.y);                            \
        u64 i2 = pack2(aiv.z), i3 = pack2(aiv.w);                            \
        fma2(T1[0][0], a0, br0); fma2(T1[0][1], a0, br1);                    \
        fma2(T1[1][0], a1, br0); fma2(T1[1][1], a1, br1);                    \
        fma2(T1[2][0], a2, br0); fma2(T1[2][1], a2, br1);                    \
        fma2(T1[3][0], a3, br0); fma2(T1[3][1], a3, br1);                    \
        fma2(T2[0][0], i0, bi0); fma2(T2[0][1], i0, bi1);                    \
        fma2(T2[1][0], i1, bi0); fma2(T2[1][1], i1, bi1);                    \
        fma2(T2[2][0], i2, bi0); fma2(T2[2][1], i2, bi1);                    \
        fma2(T2[3][0], i3, bi0); fma2(T2[3][1], i3, bi1);                    \
        add2(a0, a0, i0); add2(a1, a1, i1);                                  \
        add2(a2, a2, i2); add2(a3, a3, i3);                                  \
        fma2(T3[0][0], a0, bs0); fma2(T3[0][1], a0, bs1);                    \
        fma2(T3[1][0], a1, bs0); fma2(T3[1][1], a1, bs1);                    \
        fma2(T3[2][0], a2, bs0); fma2(T3[2][1], a2, bs1);                    \
        fma2(T3[3][0], a3, bs0); fma2(T3[3][1], a3, bs1);                    \
    }

// ======================= NN kernel: C[b] = A(b?) * U[b] ====================
// tile: BM=64, BN=64, BK=16; 256 threads; per-thread 4(M) x 4(N); 2 CTAs/SM
// Karatsuba: T1=ar*br, T2=ai*bi, T3=(ar+ai)(br+bi); cr=T1-T2, ci=T3-T1-T2
// Sum components computed in registers. Ping-pong smem double buffer:
// one __syncthreads per k-tile; LDG/STS of next tile overlaps compute.
__global__ __launch_bounds__(256, 2)
void cgemm_nn(const float* __restrict__ Are, const float* __restrict__ Aim, int strideA,
              const float* __restrict__ Ure, const float* __restrict__ Uim,
              float* __restrict__ Cre, float* __restrict__ Cim,
              int d, int rest)
{
    __shared__ __align__(16) float As_re[2][BKT][SPAD], As_im[2][BKT][SPAD];
    __shared__ __align__(16) float Bs_re[2][BKT][SPAD], Bs_im[2][BKT][SPAD];

    const int b  = blockIdx.z;
    const int m0 = blockIdx.y * 64;
    const int n0 = blockIdx.x * 64;

    const float* are = Are + (size_t)b * strideA;
    const float* aim = Aim + (size_t)b * strideA;
    const float* ure = Ure + (size_t)b * d * rest + n0;
    const float* uim = Uim + (size_t)b * d * rest + n0;
    float*       cre = Cre + (size_t)b * d * rest + n0;
    float*       cim = Cim + (size_t)b * d * rest + n0;

    const int tid = threadIdx.x;
    const int tn4 = (tid & 15) * 4;     // frag cols
    const int tm4 = (tid >> 4) * 4;     // frag rows
    const int arow = tid >> 2;          // A loader m-row 0..63
    const int ac4  = (tid & 3) * 4;     // A loader k-col
    const int ukr  = tid >> 4;          // B loader k-row 0..15
    const int un4  = (tid & 15) * 4;    // B loader col

    u64 T1[4][2], T2[4][2], T3[4][2];
#pragma unroll
    for (int i = 0; i < 4; i++)
#pragma unroll
        for (int c = 0; c < 2; c++) { T1[i][c] = 0ULL; T2[i][c] = 0ULL; T3[i][c] = 0ULL; }

    // load + store tile 0
    float4 pa_r = *(const float4*)(are + (size_t)(m0 + arow) * d + ac4);
    float4 pa_i = *(const float4*)(aim + (size_t)(m0 + arow) * d + ac4);
    float4 pb_r = *(const float4*)(ure + (size_t)ukr * rest + un4);
    float4 pb_i = *(const float4*)(uim + (size_t)ukr * rest + un4);
    As_re[0][ac4 + 0][arow] = pa_r.x; As_re[0][ac4 + 1][arow] = pa_r.y;
    As_re[0][ac4 + 2][arow] = pa_r.z; As_re[0][ac4 + 3][arow] = pa_r.w;
    As_im[0][ac4 + 0][arow] = pa_i.x; As_im[0][ac4 + 1][arow] = pa_i.y;
    As_im[0][ac4 + 2][arow] = pa_i.z; As_im[0][ac4 + 3][arow] = pa_i.w;
    *(float4*)&Bs_re[0][ukr][un4] = pb_r;
    *(float4*)&Bs_im[0][ukr][un4] = pb_i;
    __syncthreads();

    const int ntile = d / BKT;
    for (int t = 0; t < ntile; t++) {
        const int cur = t & 1;
        if (t + 1 < ntile) {    // prefetch next tile (overlaps compute below)
            const int kk = (t + 1) * BKT;
            pa_r = *(const float4*)(are + (size_t)(m0 + arow) * d + kk + ac4);
            pa_i = *(const float4*)(aim + (size_t)(m0 + arow) * d + kk + ac4);
            pb_r = *(const float4*)(ure + (size_t)(kk + ukr) * rest + un4);
            pb_i = *(const float4*)(uim + (size_t)(kk + ukr) * rest + un4);
        }

#pragma unroll
        for (int k = 0; k < BKT; k++) KSTEP(As_re[cur], As_im[cur], Bs_re[cur], Bs_im[cur], k)

        if (t + 1 < ntile) {    // store next into the other buffer, single barrier
            const int nxt = cur ^ 1;
            As_re[nxt][ac4 + 0][arow] = pa_r.x; As_re[nxt][ac4 + 1][arow] = pa_r.y;
            As_re[nxt][ac4 + 2][arow] = pa_r.z; As_re[nxt][ac4 + 3][arow] = pa_r.w;
            As_im[nxt][ac4 + 0][arow] = pa_i.x; As_im[nxt][ac4 + 1][arow] = pa_i.y;
            As_im[nxt][ac4 + 2][arow] = pa_i.z; As_im[nxt][ac4 + 3][arow] = pa_i.w;
            *(float4*)&Bs_re[nxt][ukr][un4] = pb_r;
            *(float4*)&Bs_im[nxt][ukr][un4] = pb_i;
            __syncthreads();
        }
    }

#pragma unroll
    for (int i = 0; i < 4; i++) {
        int m = m0 + tm4 + i;
        float re[4], im_[4];
#pragma unroll
        for (int c = 0; c < 2; c++) {
            float t1l, t1h, t2l, t2h, t3l, t3h;
            unpack2(t1l, t1h, T1[i][c]);
            unpack2(t2l, t2h, T2[i][c]);
            unpack2(t3l, t3h, T3[i][c]);
            re[2 * c]      = t1l - t2l;
            re[2 * c + 1]  = t1h - t2h;
            im_[2 * c]     = t3l - t1l - t2l;
            im_[2 * c + 1] = t3h - t1h - t2h;
        }
        *(float4*)(cre + (size_t)m * rest + tn4) = make_float4(re[0], re[1], re[2], re[3]);
        *(float4*)(cim + (size_t)m * rest + tn4) = make_float4(im_[0], im_[1], im_[2], im_[3]);
    }
}

// ============ NT split-K: P[chunk][b] = L[b] * U[b]^T (K chunk) ============
// tile: BM=64, BN=64, BK=16; 256 threads; per-thread 4(M) x 4(N); ping-pong.
__global__ __launch_bounds__(256, 2)
void cgemm_nt(const float* __restrict__ Lre, const float* __restrict__ Lim,
              const float* __restrict__ Ure, const float* __restrict__ Uim,
              float* __restrict__ Pre, float* __restrict__ Pim,
              int d, int K, int KC)
{
    __shared__ __align__(16) float As_re[2][BKT][SPAD], As_im[2][BKT][SPAD];
    __shared__ __align__(16) float Bs_re[2][BKT][SPAD], Bs_im[2][BKT][SPAD];

    const int bz    = blockIdx.z;
    const int b     = bz & 7;
    const int chunk = bz >> 3;
    const int m0    = blockIdx.y * 64;
    const int n0    = blockIdx.x * 64;

    const float* lre = Lre + (size_t)b * d * K;
    const float* lim = Lim + (size_t)b * d * K;
    const float* ure = Ure + (size_t)b * d * K;
    const float* uim = Uim + (size_t)b * d * K;

    const int tid = threadIdx.x;
    const int tn4 = (tid & 15) * 4;
    const int tm4 = (tid >> 4) * 4;
    const int lrr = tid >> 2;           // loader row 0..63 (both A and B)
    const int lc4 = (tid & 3) * 4;      // loader k-col

    u64 T1[4][2], T2[4][2], T3[4][2];
#pragma unroll
    for (int i = 0; i < 4; i++)
#pragma unroll
        for (int c = 0; c < 2; c++) { T1[i][c] = 0ULL; T2[i][c] = 0ULL; T3[i][c] = 0ULL; }

    const int kbeg = chunk * KC;

    float4 par = *(const float4*)(lre + (size_t)(m0 + lrr) * K + kbeg + lc4);
    float4 pai = *(const float4*)(lim + (size_t)(m0 + lrr) * K + kbeg + lc4);
    float4 pbr = *(const float4*)(ure + (size_t)(n0 + lrr) * K + kbeg + lc4);
    float4 pbi = *(const float4*)(uim + (size_t)(n0 + lrr) * K + kbeg + lc4);
    As_re[0][lc4 + 0][lrr] = par.x; As_re[0][lc4 + 1][lrr] = par.y;
    As_re[0][lc4 + 2][lrr] = par.z; As_re[0][lc4 + 3][lrr] = par.w;
    As_im[0][lc4 + 0][lrr] = pai.x; As_im[0][lc4 + 1][lrr] = pai.y;
    As_im[0][lc4 + 2][lrr] = pai.z; As_im[0][lc4 + 3][lrr] = pai.w;
    Bs_re[0][lc4 + 0][lrr] = pbr.x; Bs_re[0][lc4 + 1][lrr] = pbr.y;
    Bs_re[0][lc4 + 2][lrr] = pbr.z; Bs_re[0][lc4 + 3][lrr] = pbr.w;
    Bs_im[0][lc4 + 0][lrr] = pbi.x; Bs_im[0][lc4 + 1][lrr] = pbi.y;
    Bs_im[0][lc4 + 2][lrr] = pbi.z; Bs_im[0][lc4 + 3][lrr] = pbi.w;
    __syncthreads();

    const int ntile = KC / BKT;
    for (int t = 0; t < ntile; t++) {
        const int cur = t & 1;
        if (t + 1 < ntile) {
            const int kk = kbeg + (t + 1) * BKT;
            par = *(const float4*)(lre + (size_t)(m0 + lrr) * K + kk + lc4);
            pai = *(const float4*)(lim + (size_t)(m0 + lrr) * K + kk + lc4);
            pbr = *(const float4*)(ure + (size_t)(n0 + lrr) * K + kk + lc4);
            pbi = *(const float4*)(uim + (size_t)(n0 + lrr) * K + kk + lc4);
        }

#pragma unroll
        for (int k = 0; k < BKT; k++) KSTEP(As_re[cur], As_im[cur], Bs_re[cur], Bs_im[cur], k)

        if (t + 1 < ntile) {
            const int nxt = cur ^ 1;
            As_re[nxt][lc4 + 0][lrr] = par.x; As_re[nxt][lc4 + 1][lrr] = par.y;
            As_re[nxt][lc4 + 2][lrr] = par.z; As_re[nxt][lc4 + 3][lrr] = par.w;
            As_im[nxt][lc4 + 0][lrr] = pai.x; As_im[nxt][lc4 + 1][lrr] = pai.y;
            As_im[nxt][lc4 + 2][lrr] = pai.z; As_im[nxt][lc4 + 3][lrr] = pai.w;
            Bs_re[nxt][lc4 + 0][lrr] = pbr.x; Bs_re[nxt][lc4 + 1][lrr] = pbr.y;
            Bs_re[nxt][lc4 + 2][lrr] = pbr.z; Bs_re[nxt][lc4 + 3][lrr] = pbr.w;
            Bs_im[nxt][lc4 + 0][lrr] = pbi.x; Bs_im[nxt][lc4 + 1][lrr] = pbi.y;
            Bs_im[nxt][lc4 + 2][lrr] = pbi.z; Bs_im[nxt][lc4 + 3][lrr] = pbi.w;
            __syncthreads();
        }
    }

    size_t off = (size_t)(chunk * BATCH + b) * d * d;
#pragma unroll
    for (int i = 0; i < 4; i++) {
        int m = m0 + tm4 + i;
        float re[4], im_[4];
#pragma unroll
        for (int c = 0; c < 2; c++) {
            float t1l, t1h, t2l, t2h, t3l, t3h;
            unpack2(t1l, t1h, T1[i][c]);
            unpack2(t2l, t2h, T2[i][c]);
            unpack2(t3l, t3h, T3[i][c]);
            re[2 * c]      = t1l - t2l;
            re[2 * c + 1]  = t1h - t2h;
            im_[2 * c]     = t3l - t1l - t2l;
            im_[2 * c + 1] = t3h - t1h - t2h;
        }
        *(float4*)(Pre + off + (size_t)m * d + n0 + tn4) = make_float4(re[0], re[1], re[2], re[3]);
        *(float4*)(Pim + off + (size_t)m * d + n0 + tn4) = make_float4(im_[0], im_[1], im_[2], im_[3]);
    }
}

// ---------------- fused split-K reduce + softmax(|s|/scale)*phase ---------
__global__ void softmax_fused(const float* __restrict__ Pre, const float* __restrict__ Pim,
                              float* __restrict__ Mre, float* __restrict__ Mim,
                              int d, int n, int nchunks,
                              const float* __restrict__ logtau, float sfac)
{
    const int row = blockIdx.x;
    const int j   = threadIdx.x;
    const int idx = row * d + j;

    float sr = 0.f, si = 0.f;
    for (int c = 0; c < nchunks; c++) {
        sr += Pre[(size_t)c * n + idx];
        si += Pim[(size_t)c * n + idx];
    }
    const float mag = sqrtf(sr * sr + si * si);

    const float tau   = fmaxf(expf(logtau[0]), 1e-8f);
    const float scale = tau * sfac;
    const float logit = mag / scale;

    __shared__ float wred[4];
    __shared__ float wsum[4];
    const int warp = j >> 5, lane = j & 31, nw = d >> 5;

    float v = logit;
#pragma unroll
    for (int o = 16; o > 0; o >>= 1) v = fmaxf(v, __shfl_xor_sync(0xffffffffu, v, o));
    if (lane == 0) wred[warp] = v;
    __syncthreads();
    float mx = wred[0];
    for (int w = 1; w < nw; w++) mx = fmaxf(mx, wred[w]);

    const float e = expf(logit - mx);
    float s_ = e;
#pragma unroll
    for (int o = 16; o > 0; o >>= 1) s_ += __shfl_xor_sync(0xffffffffu, s_, o);
    if (lane == 0) wsum[warp] = s_;
    __syncthreads();
    float tot = 0.f;
    for (int w = 0; w < nw; w++) tot += wsum[w];

    const float routing = e / tot;
    float pr, pi;
    if (mag > 1e-8f) { pr = sr / mag; pi = si / mag; }
    else             { pr = 1.f;      pi = 0.f; }
    Mre[(size_t)row * d + j] = routing * pr;
    Mim[(size_t)row * d + j] = routing * pi;
}

// ---------------- mode-1 permute (float4): swap the two 128-axes ----------
__global__ void perm_swap01(const float4* __restrict__ s4re, const float4* __restrict__ s4im,
                            float4* __restrict__ d4re, float4* __restrict__ d4im)
{
    int t = blockIdx.x * 256 + threadIdx.x;     // < NTOT/4 = 2097152
    int k4 = t & 15;
    int q  = (t >> 4) & 127;
    int p  = (t >> 11) & 127;
    int b  = t >> 18;
    int src = ((((b << 7) | q) << 7) | p) << 4 | k4;
    d4re[t] = s4re[src];
    d4im[t] = s4im[src];
}

// ---------------- batched 2D transpose: dst[b][c][r] = src[b][r][c] -------
__global__ void perm_transpose(const float* __restrict__ sre, const float* __restrict__ sim,
                               float* __restrict__ dre, float* __restrict__ dim_,
                               int R, int C)
{
    __shared__ float tre[32][33], tim[32][33];
    const int b  = blockIdx.z;
    const int r0 = blockIdx.y * 32;
    const int c0 = blockIdx.x * 32;
    const float* sr_ = sre + (size_t)b * R * C;
    const float* si_ = sim + (size_t)b * R * C;
    float*       dr_ = dre + (size_t)b * R * C;
    float*       di_ = dim_ + (size_t)b * R * C;
    const int x = threadIdx.x, y = threadIdx.y;    // 32 x 8
#pragma unroll
    for (int i = y; i < 32; i += 8) {
        tre[i][x] = sr_[(size_t)(r0 + i) * C + c0 + x];
        tim[i][x] = si_[(size_t)(r0 + i) * C + c0 + x];
    }
    __syncthreads();
#pragma unroll
    for (int i = y; i < 32; i += 8) {
        dr_[(size_t)(c0 + i) * R + r0 + x] = tre[x][i];
        di_[(size_t)(c0 + i) * R + r0 + x] = tim[x][i];
    }
}

// --------------------------------------------------------------------------
extern "C" void kernel_launch(void* const* d_in, const int* in_sizes, int n_in,
                              void* d_out, int out_size)
{
    (void)in_sizes; (void)n_in; (void)out_size;
    const float* xre  = (const float*)d_in[0];
    const float* xim  = (const float*)d_in[1];
    const float* w0re = (const float*)d_in[2];
    const float* w0im = (const float*)d_in[3];
    const float* w1re = (const float*)d_in[4];
    const float* w1im = (const float*)d_in[5];
    const float* w2re = (const float*)d_in[6];
    const float* w2im = (const float*)d_in[7];
    const float* ltau = (const float*)d_in[8];
    float* out_re = (float*)d_out;
    float* out_im = out_re + (size_t)NTOT;

    float *s_re, *s_im, *u_re, *u_im, *l_re, *l_im, *p_re, *p_im, *m_re, *m_im;
    cudaGetSymbolAddress((void**)&s_re,  g_s_re);
    cudaGetSymbolAddress((void**)&s_im,  g_s_im);
    cudaGetSymbolAddress((void**)&u_re,  g_u_re);
    cudaGetSymbolAddress((void**)&u_im,  g_u_im);
    cudaGetSymbolAddress((void**)&l_re,  g_l_re);
    cudaGetSymbolAddress((void**)&l_im,  g_l_im);
    cudaGetSymbolAddress((void**)&p_re,  g_p_re);
    cudaGetSymbolAddress((void**)&p_im,  g_p_im);
    cudaGetSymbolAddress((void**)&m_re,  g_m_re);
    cudaGetSymbolAddress((void**)&m_im,  g_m_im);

    // ---------------- Mode 0: d=128, rest=8192 (unfold = identity) --------
    {
        const int d = 128, rest = 8192;
        dim3 g1(rest / 64, d / 64, BATCH);
        cgemm_nn<<<g1, 256>>>(w0re, w0im, 0, xre, xim, l_re, l_im, d, rest);

        const int NC = 32, KC = rest / NC;        // 256
        dim3 g2(d / 64, d / 64, BATCH * NC);
        cgemm_nt<<<g2, 256>>>(l_re, l_im, xre, xim, p_re, p_im, d, rest, KC);

        const int n = BATCH * d * d;
        softmax_fused<<<BATCH * d, d>>>(p_re, p_im, m_re, m_im, d, n, NC, ltau,
                                        sqrtf((float)SS / (float)d));
        cgemm_nn<<<g1, 256>>>(m_re, m_im, d * d, xre, xim, s_re, s_im, d, rest);
    }

    // ---------------- Mode 1: d=128, rest=8192 ----------------------------
    {
        const int d = 128, rest = 8192;
        perm_swap01<<<(NTOT / 4) / 256, 256>>>((const float4*)s_re, (const float4*)s_im,
                                               (float4*)u_re, (float4*)u_im);

        dim3 g1(rest / 64, d / 64, BATCH);
        cgemm_nn<<<g1, 256>>>(w1re, w1im, 0, u_re, u_im, l_re, l_im, d, rest);

        const int NC = 32, KC = rest / NC;
        dim3 g2(d / 64, d / 64, BATCH * NC);
        cgemm_nt<<<g2, 256>>>(l_re, l_im, u_re, u_im, p_re, p_im, d, rest, KC);

        const int n = BATCH * d * d;
        softmax_fused<<<BATCH * d, d>>>(p_re, p_im, m_re, m_im, d, n, NC, ltau,
                                        sqrtf((float)SS / (float)d));
        cgemm_nn<<<g1, 256>>>(m_re, m_im, d * d, u_re, u_im, l_re, l_im, d, rest);
        perm_swap01<<<(NTOT / 4) / 256, 256>>>((const float4*)l_re, (const float4*)l_im,
                                               (float4*)s_re, (float4*)s_im);
    }

    // ---------------- Mode 2: d=64, rest=16384 ----------------------------
    {
        const int d = 64, rest = 16384;
        // unfold: u[b, k, p] = s[b, p, k]   (src R=16384, C=64)
        dim3 gt(64 / 32, 16384 / 32, BATCH);
        perm_transpose<<<gt, dim3(32, 8)>>>(s_re, s_im, u_re, u_im, 16384, 64);

        dim3 g1(rest / 64, d / 64, BATCH);
        cgemm_nn<<<g1, 256>>>(w2re, w2im, 0, u_re, u_im, l_re, l_im, d, rest);

        const int NC = 64, KC = rest / NC;        // 256
        dim3 g2(d / 64, d / 64, BATCH * NC);
        cgemm_nt<<<g2, 256>>>(l_re, l_im, u_re, u_im, p_re, p_im, d, rest, KC);

        const int n = BATCH * d * d;
        softmax_fused<<<BATCH * d, d>>>(p_re, p_im, m_re, m_im, d, n, NC, ltau,
                                        sqrtf((float)SS / (float)d));
        cgemm_nn<<<g1, 256>>>(m_re, m_im, d * d, u_re, u_im, l_re, l_im, d, rest);

        // fold: out[b, p, k] = mixed[b, k, p]   (src R=64, C=16384) -> d_out
        dim3 gt2(16384 / 32, 64 / 32, BATCH);
        perm_transpose<<<gt2, dim3(32, 8)>>>(l_re, l_im, out_re, out_im, 64, 16384);
    }
}

// round 12
// speedup vs baseline: 1.3253x; 1.0734x over previous
#include <cuda_runtime.h>
#include <cuda_bf16.h>
#include <math.h>

#define BATCH 8
#define SS 1048576              // 128*128*64
#define NTOT (BATCH * SS)       // 8388608 per component
#define ALP 131072              // A-limb plane stride (B*128*128 max)
#define UTP NTOT                // UT-limb plane stride

// ---------------- scratch (device globals; no allocation) ----------------
__device__ float g_s_re[NTOT];
__device__ float g_s_im[NTOT];
__device__ float g_u_re[NTOT];
__device__ float g_u_im[NTOT];
__device__ float g_l_re[NTOT];
__device__ float g_l_im[NTOT];
__device__ float g_p_re[4194304];
__device__ float g_p_im[4194304];
__device__ float g_m_re[131072];
__device__ float g_m_im[131072];
__device__ __nv_bfloat16 g_abf[4 * ALP];   // A limbs: rhi,rlo,ihi,ilo
__device__ __nv_bfloat16 g_utbf[4 * UTP];  // U^T limbs: rhi,rlo,ihi,ilo

typedef unsigned long long u64;

// ================= limb conversion kernels ================================
__global__ void conv_limbs_A(const float* __restrict__ re, const float* __restrict__ im,
                             __nv_bfloat16* __restrict__ out, int n)
{
    int i = blockIdx.x * 256 + threadIdx.x;
    if (i >= n) return;
    float x = re[i];
    __nv_bfloat16 h = __float2bfloat16(x);
    out[0 * ALP + i] = h;
    out[1 * ALP + i] = __float2bfloat16(x - __bfloat162float(h));
    float y = im[i];
    __nv_bfloat16 ih = __float2bfloat16(y);
    out[2 * ALP + i] = ih;
    out[3 * ALP + i] = __float2bfloat16(y - __bfloat162float(ih));
}

// transpose + limb split: U (B, d, rest) fp32 -> UT planes (B, rest, d) bf16
__global__ void conv_ut(const float* __restrict__ ure, const float* __restrict__ uim,
                        __nv_bfloat16* __restrict__ out, int d, int rest)
{
    __shared__ float tr[32][33], ti[32][33];
    const int b  = blockIdx.z;
    const int k0 = blockIdx.y * 32;       // d index
    const int n0 = blockIdx.x * 32;       // rest index
    const size_t ib = (size_t)b * d * rest;
    const size_t ob = (size_t)b * rest * d;
    const int x = threadIdx.x, y = threadIdx.y;   // 32 x 8
#pragma unroll
    for (int i = y; i < 32; i += 8) {
        tr[i][x] = ure[ib + (size_t)(k0 + i) * rest + n0 + x];
        ti[i][x] = uim[ib + (size_t)(k0 + i) * rest + n0 + x];
    }
    __syncthreads();
#pragma unroll
    for (int i = y; i < 32; i += 8) {
        size_t o = ob + (size_t)(n0 + i) * d + k0 + x;
        float xr = tr[x][i], xi = ti[x][i];
        __nv_bfloat16 rh = __float2bfloat16(xr);
        __nv_bfloat16 ihh = __float2bfloat16(xi);
        out[0 * (size_t)UTP + o] = rh;
        out[1 * (size_t)UTP + o] = __float2bfloat16(xr - __bfloat162float(rh));
        out[2 * (size_t)UTP + o] = ihh;
        out[3 * (size_t)UTP + o] = __float2bfloat16(xi - __bfloat162float(ihh));
    }
}

// ================= mma.sync helpers =======================================
__device__ __forceinline__ unsigned smem_u32(const void* p) {
    unsigned a;
    asm("{ .reg .u64 t; cvta.to.shared.u64 t, %1; cvt.u32.u64 %0, t; }"
        : "=r"(a) : "l"(p));
    return a;
}
__device__ __forceinline__ void ldm_x4(unsigned* r, unsigned addr) {
    asm volatile("ldmatrix.sync.aligned.m8n8.x4.shared.b16 {%0,%1,%2,%3}, [%4];"
                 : "=r"(r[0]), "=r"(r[1]), "=r"(r[2]), "=r"(r[3]) : "r"(addr));
}
__device__ __forceinline__ void mma16816(float* c, const unsigned* a, const unsigned* b) {
    asm volatile(
        "mma.sync.aligned.m16n8k16.row.col.f32.bf16.bf16.f32 "
        "{%0,%1,%2,%3}, {%4,%5,%6,%7}, {%8,%9}, {%0,%1,%2,%3};"
        : "+f"(c[0]), "+f"(c[1]), "+f"(c[2]), "+f"(c[3])
        : "r"(a[0]), "r"(a[1]), "r"(a[2]), "r"(a[3]), "r"(b[0]), "r"(b[1]));
}

// ================= tensor-core NN: C[b] = A(b?) * U[b] ====================
// D[m][n] = sum_k A[m][k] * UT[n][k]; A limbs (d x d), UT limbs (rest x d).
// CTA tile 64(M) x 128(N), 8 warps (2m x 4n), warp tile 32x32, K chunks of 32.
// Limb scheme (planes 0..3 = rh, rl, ih, il):
//   cr += Arh*Brh + Arh*Brl + Arl*Brh - (Aih*Bih + Aih*Bil + Ail*Bih)
//   ci += Arh*Bih + Arh*Bil + Arl*Bih +  Aih*Brh + Aih*Brl + Ail*Brh
// (negation done on the A-ih/il fragments via XOR sign bits)
#define APITCH 40               // halves per A/B smem row (80B: conflict-free)
#define APL (64 * APITCH)       // halves per A plane
#define BPL (128 * APITCH)      // halves per B plane
#define SMEM_TN ((4 * APL + 4 * BPL) * 2)   // 61440 bytes

__global__ void __launch_bounds__(256, 1)
tensor_nn(const __nv_bfloat16* __restrict__ Ab, int strideAb,
          const __nv_bfloat16* __restrict__ UTb,
          float* __restrict__ Cre, float* __restrict__ Cim,
          int d, int rest)
{
    extern __shared__ __align__(16) char smem[];
    __nv_bfloat16* As = (__nv_bfloat16*)smem;                 // [4][64][APITCH]
    __nv_bfloat16* Bs = (__nv_bfloat16*)(smem + 4 * APL * 2); // [4][128][APITCH]

    const int tid = threadIdx.x, lane = tid & 31, wid = tid >> 5;
    const int b = blockIdx.z, m0 = blockIdx.y * 64, n0 = blockIdx.x * 128;
    const int wm = wid >> 2, wn = wid & 3;

    // ldmatrix lane-role decode
    const int rsel = lane >> 3, l8 = lane & 7;
    const int aro = (rsel & 1) ? 8 : 0, ako = (rsel & 2) ? 8 : 0;   // A: r0 rows0-7 k0-7, r1 rows8-15 k0-7, r2 rows0-7 k8-15, r3 rows8-15 k8-15
    const int bko = (rsel & 1) ? 8 : 0, bro = (rsel & 2) ? 8 : 0;   // B: r0 n0-7 k0-7, r1 n0-7 k8-15, r2 n8-15 k0-7, r3 n8-15 k8-15

    float cr[2][4][4], ci[2][4][4];
#pragma unroll
    for (int mi = 0; mi < 2; mi++)
#pragma unroll
        for (int ns = 0; ns < 4; ns++)
#pragma unroll
            for (int q = 0; q < 4; q++) { cr[mi][ns][q] = 0.f; ci[mi][ns][q] = 0.f; }

    const int nchunks = d / 32;
    for (int c = 0; c < nchunks; c++) {
        // ---- load A planes: 4 x 64 rows x 32 halves = 1024 uint4 ----
        for (int u = tid; u < 1024; u += 256) {
            int p = u >> 8, v = u & 255;
            int r = v >> 2, j = v & 3;
            uint4 s = *(const uint4*)(Ab + (size_t)p * ALP + (size_t)b * strideAb
                                      + (size_t)(m0 + r) * d + c * 32 + j * 8);
            *(uint4*)(As + p * APL + r * APITCH + j * 8) = s;
        }
        // ---- load B planes: 4 x 128 rows x 32 halves = 2048 uint4 ----
        for (int u = tid; u < 2048; u += 256) {
            int p = u >> 9, v = u & 511;
            int r = v >> 2, j = v & 3;
            uint4 s = *(const uint4*)(UTb + (size_t)p * UTP + (size_t)b * rest * d
                                      + (size_t)(n0 + r) * d + c * 32 + j * 8);
            *(uint4*)(Bs + p * BPL + r * APITCH + j * 8) = s;
        }
        __syncthreads();

#pragma unroll
        for (int s = 0; s < 2; s++) {           // two k16 steps per chunk
            // B fragments: bf[plane][gj][4]; r0,r1 = n-sub (2gj), r2,r3 = n-sub (2gj+1)
            unsigned bf[4][2][4];
#pragma unroll
            for (int p = 0; p < 4; p++)
#pragma unroll
                for (int gj = 0; gj < 2; gj++) {
                    unsigned addr = smem_u32(Bs + p * BPL
                        + (wn * 32 + gj * 16 + bro + l8) * APITCH + s * 16 + bko);
                    ldm_x4(bf[p][gj], addr);
                }

#pragma unroll
            for (int mi = 0; mi < 2; mi++) {
                unsigned af[4][4];
#pragma unroll
                for (int p = 0; p < 4; p++) {
                    unsigned addr = smem_u32(As + p * APL
                        + (wm * 32 + mi * 16 + aro + l8) * APITCH + s * 16 + ako);
                    ldm_x4(af[p], addr);
                }
                unsigned nih[4], nil_[4];
#pragma unroll
                for (int q = 0; q < 4; q++) {
                    nih[q]  = af[2][q] ^ 0x80008000u;
                    nil_[q] = af[3][q] ^ 0x80008000u;
                }
#pragma unroll
                for (int ns = 0; ns < 4; ns++) {
                    const unsigned* brh = &bf[0][ns >> 1][(ns & 1) * 2];
                    const unsigned* brl = &bf[1][ns >> 1][(ns & 1) * 2];
                    const unsigned* bih = &bf[2][ns >> 1][(ns & 1) * 2];
                    const unsigned* bil = &bf[3][ns >> 1][(ns & 1) * 2];
                    float* pcr = cr[mi][ns];
                    float* pci = ci[mi][ns];
                    mma16816(pcr, af[0], brh);
                    mma16816(pcr, af[0], brl);
                    mma16816(pcr, af[1], brh);
                    mma16816(pcr, nih,   bih);
                    mma16816(pcr, nih,   bil);
                    mma16816(pcr, nil_,  bih);
                    mma16816(pci, af[0], bih);
                    mma16816(pci, af[0], bil);
                    mma16816(pci, af[1], bih);
                    mma16816(pci, af[2], brh);
                    mma16816(pci, af[2], brl);
                    mma16816(pci, af[3], brh);
                }
            }
        }
        __syncthreads();
    }

    // ---- epilogue: C frags -> gmem (c0,c1)=row g, (c2,c3)=row g+8 --------
    const int g = lane >> 2, t = lane & 3;
    float* crebase = Cre + (size_t)b * d * rest;
    float* cimbase = Cim + (size_t)b * d * rest;
#pragma unroll
    for (int mi = 0; mi < 2; mi++) {
        int mrow = m0 + wm * 32 + mi * 16 + g;
#pragma unroll
        for (int ns = 0; ns < 4; ns++) {
            int col = n0 + wn * 32 + ns * 8 + 2 * t;
            *(float2*)(crebase + (size_t)mrow * rest + col) =
                make_float2(cr[mi][ns][0], cr[mi][ns][1]);
            *(float2*)(crebase + (size_t)(mrow + 8) * rest + col) =
                make_float2(cr[mi][ns][2], cr[mi][ns][3]);
            *(float2*)(cimbase + (size_t)mrow * rest + col) =
                make_float2(ci[mi][ns][0], ci[mi][ns][1]);
            *(float2*)(cimbase + (size_t)(mrow + 8) * rest + col) =
                make_float2(ci[mi][ns][2], ci[mi][ns][3]);
        }
    }
}

// ================= SIMT NT split-K (unchanged, proven) ====================
__device__ __forceinline__ u64 pack2(float x) {
    unsigned xi = __float_as_uint(x);
    u64 r;
    asm("mov.b64 %0, {%1,%2};" : "=l"(r) : "r"(xi), "r"(xi));
    return r;
}
__device__ __forceinline__ void fma2(u64& d, u64 a, u64 b) {
    asm("fma.rn.f32x2 %0, %1, %2, %3;" : "=l"(d) : "l"(a), "l"(b), "l"(d));
}
__device__ __forceinline__ void add2(u64& d, u64 a, u64 b) {
    asm("add.rn.f32x2 %0, %1, %2;" : "=l"(d) : "l"(a), "l"(b));
}
__device__ __forceinline__ void lds2(u64& lo, u64& hi, const float* p) {
    unsigned a = (unsigned)__cvta_generic_to_shared(p);
    asm volatile("ld.shared.v2.b64 {%0,%1}, [%2];" : "=l"(lo), "=l"(hi) : "r"(a));
}
__device__ __forceinline__ void unpack2(float& lo, float& hi, u64 v) {
    unsigned a, b;
    asm("mov.b64 {%0,%1}, %2;" : "=r"(a), "=r"(b) : "l"(v));
    lo = __uint_as_float(a); hi = __uint_as_float(b);
}

#define BKT 16
#define SPAD 68

#define KSTEP(Asr, Asi, Bsr, Bsi, k)                                         \
    {                                                                        \
        u64 br0, br1, bi0, bi1, bs0, bs1;                                    \
        lds2(br0, br1, &Bsr[k][tn4]);                                        \
        lds2(bi0, bi1, &Bsi[k][tn4]);                                        \
        add2(bs0, br0, bi0); add2(bs1, br1, bi1);                            \
        float4 arv = *(const float4*)&Asr[k][tm4];                           \
        float4 aiv = *(const float4*)&Asi[k][tm4];                           \
        u64 a0 = pack2(arv.x), a1 = pack2(arv.y);                            \
        u64 a2 = pack2(arv.z), a3 = pack2(arv.w);                            \
        u64 i0 = pack2(aiv.x), i1 = pack2(aiv.y);                            \
        u64 i2 = pack2(aiv.z), i3 = pack2(aiv.w);                            \
        fma2(T1[0][0], a0, br0); fma2(T1[0][1], a0, br1);                    \
        fma2(T1[1][0], a1, br0); fma2(T1[1][1], a1, br1);                    \
        fma2(T1[2][0], a2, br0); fma2(T1[2][1], a2, br1);                    \
        fma2(T1[3][0], a3, br0); fma2(T1[3][1], a3, br1);                    \
        fma2(T2[0][0], i0, bi0); fma2(T2[0][1], i0, bi1);                    \
        fma2(T2[1][0], i1, bi0); fma2(T2[1][1], i1, bi1);                    \
        fma2(T2[2][0], i2, bi0); fma2(T2[2][1], i2, bi1);                    \
        fma2(T2[3][0], i3, bi0); fma2(T2[3][1], i3, bi1);                    \
        add2(a0, a0, i0); add2(a1, a1, i1);                                  \
        add2(a2, a2, i2); add2(a3, a3, i3);                                  \
        fma2(T3[0][0], a0, bs0); fma2(T3[0][1], a0, bs1);                    \
        fma2(T3[1][0], a1, bs0); fma2(T3[1][1], a1, bs1);                    \
        fma2(T3[2][0], a2, bs0); fma2(T3[2][1], a2, bs1);                    \
        fma2(T3[3][0], a3, bs0); fma2(T3[3][1], a3, bs1);                    \
    }

__global__ __launch_bounds__(256, 2)
void cgemm_nt(const float* __restrict__ Lre, const float* __restrict__ Lim,
              const float* __restrict__ Ure, const float* __restrict__ Uim,
              float* __restrict__ Pre, float* __restrict__ Pim,
              int d, int K, int KC)
{
    __shared__ __align__(16) float As_re[BKT][SPAD], As_im[BKT][SPAD];
    __shared__ __align__(16) float Bs_re[BKT][SPAD], Bs_im[BKT][SPAD];

    const int bz    = blockIdx.z;
    const int b     = bz & 7;
    const int chunk = bz >> 3;
    const int m0    = blockIdx.y * 64;
    const int n0    = blockIdx.x * 64;

    const float* lre = Lre + (size_t)b * d * K;
    const float* lim = Lim + (size_t)b * d * K;
    const float* ure = Ure + (size_t)b * d * K;
    const float* uim = Uim + (size_t)b * d * K;

    const int tid = threadIdx.x;
    const int tn4 = (tid & 15) * 4;
    const int tm4 = (tid >> 4) * 4;
    const int lrr = tid >> 2;
    const int lc4 = (tid & 3) * 4;

    u64 T1[4][2], T2[4][2], T3[4][2];
#pragma unroll
    for (int i = 0; i < 4; i++)
#pragma unroll
        for (int c = 0; c < 2; c++) { T1[i][c] = 0ULL; T2[i][c] = 0ULL; T3[i][c] = 0ULL; }

    const int kbeg = chunk * KC;
    const int kend = kbeg + KC;

    float4 par = *(const float4*)(lre + (size_t)(m0 + lrr) * K + kbeg + lc4);
    float4 pai = *(const float4*)(lim + (size_t)(m0 + lrr) * K + kbeg + lc4);
    float4 pbr = *(const float4*)(ure + (size_t)(n0 + lrr) * K + kbeg + lc4);
    float4 pbi = *(const float4*)(uim + (size_t)(n0 + lrr) * K + kbeg + lc4);

    for (int kk = kbeg; kk < kend; kk += BKT) {
        As_re[lc4 + 0][lrr] = par.x; As_re[lc4 + 1][lrr] = par.y;
        As_re[lc4 + 2][lrr] = par.z; As_re[lc4 + 3][lrr] = par.w;
        As_im[lc4 + 0][lrr] = pai.x; As_im[lc4 + 1][lrr] = pai.y;
        As_im[lc4 + 2][lrr] = pai.z; As_im[lc4 + 3][lrr] = pai.w;
        Bs_re[lc4 + 0][lrr] = pbr.x; Bs_re[lc4 + 1][lrr] = pbr.y;
        Bs_re[lc4 + 2][lrr] = pbr.z; Bs_re[lc4 + 3][lrr] = pbr.w;
        Bs_im[lc4 + 0][lrr] = pbi.x; Bs_im[lc4 + 1][lrr] = pbi.y;
        Bs_im[lc4 + 2][lrr] = pbi.z; Bs_im[lc4 + 3][lrr] = pbi.w;
        __syncthreads();

        if (kk + BKT < kend) {
            par = *(const float4*)(lre + (size_t)(m0 + lrr) * K + kk + BKT + lc4);
            pai = *(const float4*)(lim + (size_t)(m0 + lrr) * K + kk + BKT + lc4);
            pbr = *(const float4*)(ure + (size_t)(n0 + lrr) * K + kk + BKT + lc4);
            pbi = *(const float4*)(uim + (size_t)(n0 + lrr) * K + kk + BKT + lc4);
        }

#pragma unroll
        for (int k = 0; k < BKT; k++) KSTEP(As_re, As_im, Bs_re, Bs_im, k)
        __syncthreads();
    }

    size_t off = (size_t)(chunk * BATCH + b) * d * d;
#pragma unroll
    for (int i = 0; i < 4; i++) {
        int m = m0 + tm4 + i;
        float re[4], im_[4];
#pragma unroll
        for (int c = 0; c < 2; c++) {
            float t1l, t1h, t2l, t2h, t3l, t3h;
            unpack2(t1l, t1h, T1[i][c]);
            unpack2(t2l, t2h, T2[i][c]);
            unpack2(t3l, t3h, T3[i][c]);
            re[2 * c]      = t1l - t2l;
            re[2 * c + 1]  = t1h - t2h;
            im_[2 * c]     = t3l - t1l - t2l;
            im_[2 * c + 1] = t3h - t1h - t2h;
        }
        *(float4*)(Pre + off + (size_t)m * d + n0 + tn4) = make_float4(re[0], re[1], re[2], re[3]);
        *(float4*)(Pim + off + (size_t)m * d + n0 + tn4) = make_float4(im_[0], im_[1], im_[2], im_[3]);
    }
}

// ---------------- fused split-K reduce + softmax(|s|/scale)*phase ---------
__global__ void softmax_fused(const float* __restrict__ Pre, const float* __restrict__ Pim,
                              float* __restrict__ Mre, float* __restrict__ Mim,
                              int d, int n, int nchunks,
                              const float* __restrict__ logtau, float sfac)
{
    const int row = blockIdx.x;
    const int j   = threadIdx.x;
    const int idx = row * d + j;

    float sr = 0.f, si = 0.f;
    for (int c = 0; c < nchunks; c++) {
        sr += Pre[(size_t)c * n + idx];
        si += Pim[(size_t)c * n + idx];
    }
    const float mag = sqrtf(sr * sr + si * si);

    const float tau   = fmaxf(expf(logtau[0]), 1e-8f);
    const float scale = tau * sfac;
    const float logit = mag / scale;

    __shared__ float wred[4];
    __shared__ float wsum[4];
    const int warp = j >> 5, lane = j & 31, nw = d >> 5;

    float v = logit;
#pragma unroll
    for (int o = 16; o > 0; o >>= 1) v = fmaxf(v, __shfl_xor_sync(0xffffffffu, v, o));
    if (lane == 0) wred[warp] = v;
    __syncthreads();
    float mx = wred[0];
    for (int w = 1; w < nw; w++) mx = fmaxf(mx, wred[w]);

    const float e = expf(logit - mx);
    float s_ = e;
#pragma unroll
    for (int o = 16; o > 0; o >>= 1) s_ += __shfl_xor_sync(0xffffffffu, s_, o);
    if (lane == 0) wsum[warp] = s_;
    __syncthreads();
    float tot = 0.f;
    for (int w = 0; w < nw; w++) tot += wsum[w];

    const float routing = e / tot;
    float pr, pi;
    if (mag > 1e-8f) { pr = sr / mag; pi = si / mag; }
    else             { pr = 1.f;      pi = 0.f; }
    Mre[(size_t)row * d + j] = routing * pr;
    Mim[(size_t)row * d + j] = routing * pi;
}

// ---------------- permutes (unchanged) ------------------------------------
__global__ void perm_swap01(const float4* __restrict__ s4re, const float4* __restrict__ s4im,
                            float4* __restrict__ d4re, float4* __restrict__ d4im)
{
    int t = blockIdx.x * 256 + threadIdx.x;
    int k4 = t & 15;
    int q  = (t >> 4) & 127;
    int p  = (t >> 11) & 127;
    int b  = t >> 18;
    int src = ((((b << 7) | q) << 7) | p) << 4 | k4;
    d4re[t] = s4re[src];
    d4im[t] = s4im[src];
}

__global__ void perm_transpose(const float* __restrict__ sre, const float* __restrict__ sim,
                               float* __restrict__ dre, float* __restrict__ dim_,
                               int R, int C)
{
    __shared__ float tre[32][33], tim[32][33];
    const int b  = blockIdx.z;
    const int r0 = blockIdx.y * 32;
    const int c0 = blockIdx.x * 32;
    const float* sr_ = sre + (size_t)b * R * C;
    const float* si_ = sim + (size_t)b * R * C;
    float*       dr_ = dre + (size_t)b * R * C;
    float*       di_ = dim_ + (size_t)b * R * C;
    const int x = threadIdx.x, y = threadIdx.y;
#pragma unroll
    for (int i = y; i < 32; i += 8) {
        tre[i][x] = sr_[(size_t)(r0 + i) * C + c0 + x];
        tim[i][x] = si_[(size_t)(r0 + i) * C + c0 + x];
    }
    __syncthreads();
#pragma unroll
    for (int i = y; i < 32; i += 8) {
        dr_[(size_t)(c0 + i) * R + r0 + x] = tre[x][i];
        di_[(size_t)(c0 + i) * R + r0 + x] = tim[x][i];
    }
}

// --------------------------------------------------------------------------
extern "C" void kernel_launch(void* const* d_in, const int* in_sizes, int n_in,
                              void* d_out, int out_size)
{
    (void)in_sizes; (void)n_in; (void)out_size;
    const float* xre  = (const float*)d_in[0];
    const float* xim  = (const float*)d_in[1];
    const float* wre[3] = {(const float*)d_in[2], (const float*)d_in[4], (const float*)d_in[6]};
    const float* wim[3] = {(const float*)d_in[3], (const float*)d_in[5], (const float*)d_in[7]};
    const float* ltau = (const float*)d_in[8];
    float* out_re = (float*)d_out;
    float* out_im = out_re + (size_t)NTOT;

    float *s_re, *s_im, *u_re, *u_im, *l_re, *l_im, *p_re, *p_im, *m_re, *m_im;
    __nv_bfloat16 *abf, *utbf;
    cudaGetSymbolAddress((void**)&s_re,  g_s_re);
    cudaGetSymbolAddress((void**)&s_im,  g_s_im);
    cudaGetSymbolAddress((void**)&u_re,  g_u_re);
    cudaGetSymbolAddress((void**)&u_im,  g_u_im);
    cudaGetSymbolAddress((void**)&l_re,  g_l_re);
    cudaGetSymbolAddress((void**)&l_im,  g_l_im);
    cudaGetSymbolAddress((void**)&p_re,  g_p_re);
    cudaGetSymbolAddress((void**)&p_im,  g_p_im);
    cudaGetSymbolAddress((void**)&m_re,  g_m_re);
    cudaGetSymbolAddress((void**)&m_im,  g_m_im);
    cudaGetSymbolAddress((void**)&abf,   g_abf);
    cudaGetSymbolAddress((void**)&utbf,  g_utbf);

    cudaFuncSetAttribute(tensor_nn, cudaFuncAttributeMaxDynamicSharedMemorySize, SMEM_TN);

    for (int mode = 0; mode < 3; mode++) {
        const int d    = (mode < 2) ? 128 : 64;
        const int rest = SS / d;
        const float sfac = sqrtf((float)SS / (float)d);

        // ---- unfold into u (mode0: u = x directly) ----
        const float *cu_re, *cu_im;
        if (mode == 0) { cu_re = xre; cu_im = xim; }
        else if (mode == 1) {
            perm_swap01<<<(NTOT / 4) / 256, 256>>>((const float4*)s_re, (const float4*)s_im,
                                                   (float4*)u_re, (float4*)u_im);
            cu_re = u_re; cu_im = u_im;
        } else {
            dim3 gt(64 / 32, 16384 / 32, BATCH);
            perm_transpose<<<gt, dim3(32, 8)>>>(s_re, s_im, u_re, u_im, 16384, 64);
            cu_re = u_re; cu_im = u_im;
        }

        // ---- conversions ----
        conv_ut<<<dim3(rest / 32, d / 32, BATCH), dim3(32, 8)>>>(cu_re, cu_im, utbf, d, rest);
        conv_limbs_A<<<(d * d + 255) / 256, 256>>>(wre[mode], wim[mode], abf, d * d);

        // ---- NN1 (tensor): l = W * u ----
        dim3 gnn(rest / 128, d / 64, BATCH);
        tensor_nn<<<gnn, 256, SMEM_TN>>>(abf, 0, utbf, l_re, l_im, d, rest);

        // ---- NT (SIMT split-K): score partials = l * u^T ----
        const int NC = (mode < 2) ? 32 : 64;
        const int KC = rest / NC;
        dim3 g2(d / 64, d / 64, BATCH * NC);
        cgemm_nt<<<g2, 256>>>(l_re, l_im, cu_re, cu_im, p_re, p_im, d, rest, KC);

        // ---- softmax + phase -> m ----
        const int n = BATCH * d * d;
        softmax_fused<<<BATCH * d, d>>>(p_re, p_im, m_re, m_im, d, n, NC, ltau, sfac);

        // ---- NN2 (tensor): mixed = m * u ----
        conv_limbs_A<<<(n + 255) / 256, 256>>>(m_re, m_im, abf, n);
        float* o_re = (mode == 0) ? s_re : l_re;
        float* o_im = (mode == 0) ? s_im : l_im;
        tensor_nn<<<gnn, 256, SMEM_TN>>>(abf, d * d, utbf, o_re, o_im, d, rest);

        // ---- fold back ----
        if (mode == 1) {
            perm_swap01<<<(NTOT / 4) / 256, 256>>>((const float4*)l_re, (const float4*)l_im,
                                                   (float4*)s_re, (float4*)s_im);
        } else if (mode == 2) {
            dim3 gt2(16384 / 32, 64 / 32, BATCH);
            perm_transpose<<<gt2, dim3(32, 8)>>>(l_re, l_im, out_re, out_im, 64, 16384);
        }
    }
}